// round 4
// baseline (speedup 1.0000x reference)
#include <cuda_runtime.h>
#include <math.h>
#include <stdint.h>

// Problem constants (fixed by the reference)
#define NQ    900
#define BATCH 8
#define NTOK  (NQ*BATCH)        // 7200
#define DMODEL 256
#define HEADS 8
#define DH    32
#define NLV   4
#define NPT   4
#define DFF   1024
#define S_TOT 19947
#define MTOK  (S_TOT*BATCH)     // 159576

// ---------------- scratch (static device arrays; no allocation) -------------
__device__ float g_qkv[NTOK*768];
__device__ float g_o  [NTOK*DMODEL];
__device__ float g_t2 [NTOK*DMODEL];
__device__ float g_off[NTOK*256];
__device__ float g_aw [NTOK*128];
__device__ float g_sx [NTOK*HEADS*16];
__device__ float g_sy [NTOK*HEADS*16];
__device__ float g_sw [NTOK*HEADS*16];
__device__ float g_val[(size_t)MTOK*DMODEL];
__device__ float g_ca [NTOK*DMODEL];
__device__ float g_t3 [NTOK*DMODEL];
__device__ float g_ffn[NTOK*DFF];

// ---------------- fast exp (FMA pipe, avoids MUFU bottleneck) ---------------
__device__ __forceinline__ float fexp(float x) {
    x = fmaxf(x, -80.f);
    float t  = x * 1.4426950408889634f;
    float fl = floorf(t);
    float f  = t - fl;
    float p  = 1.5403530e-4f;
    p = fmaf(p, f, 1.3333558e-3f);
    p = fmaf(p, f, 9.6181291e-3f);
    p = fmaf(p, f, 5.5504109e-2f);
    p = fmaf(p, f, 2.4022651e-1f);
    p = fmaf(p, f, 6.9314718e-1f);
    p = fmaf(p, f, 1.0f);
    int ei = (int)fl;
    float sc = __int_as_float((ei + 127) << 23);
    return p * sc;
}

// ---------------- generic NT SGEMM:  C[n,f] = A[n,:]·W[f,:] + bias ----------
// A row-major [N,K]; W row-major [F,K] (all torch-style [out,in] weights).
// Optional: A2 (A := A+A2), residual (C += Res), relu.
__global__ void __launch_bounds__(256)
gemm_nt(const float* __restrict__ A, const float* __restrict__ A2,
        const float* __restrict__ W, const float* __restrict__ bias,
        const float* __restrict__ Res, float* __restrict__ C,
        int N, int F, int K, int ldc, int coff, int relu)
{
    __shared__ float As[8][132];
    __shared__ float Ws[8][132];
    const int tid = threadIdx.x;
    const int tx = tid & 15, ty = tid >> 4;
    const int row0 = blockIdx.y * 128, col0 = blockIdx.x * 128;
    float acc[8][8];
#pragma unroll
    for (int i = 0; i < 8; i++)
#pragma unroll
        for (int j = 0; j < 8; j++) acc[i][j] = 0.f;

    const int lr = tid >> 1;        // 0..127
    const int lk = (tid & 1) * 4;   // 0 or 4

    for (int kt = 0; kt < K; kt += 8) {
        float4 av = make_float4(0.f, 0.f, 0.f, 0.f);
        int ga = row0 + lr;
        if (ga < N) {
            av = *(const float4*)(A + (size_t)ga * K + kt + lk);
            if (A2) {
                float4 b4 = *(const float4*)(A2 + (size_t)ga * K + kt + lk);
                av.x += b4.x; av.y += b4.y; av.z += b4.z; av.w += b4.w;
            }
        }
        As[lk + 0][lr] = av.x; As[lk + 1][lr] = av.y;
        As[lk + 2][lr] = av.z; As[lk + 3][lr] = av.w;

        float4 wv = make_float4(0.f, 0.f, 0.f, 0.f);
        int gw = col0 + lr;
        if (gw < F)
            wv = *(const float4*)(W + (size_t)gw * K + kt + lk);
        Ws[lk + 0][lr] = wv.x; Ws[lk + 1][lr] = wv.y;
        Ws[lk + 2][lr] = wv.z; Ws[lk + 3][lr] = wv.w;

        __syncthreads();
#pragma unroll
        for (int k = 0; k < 8; k++) {
            float ar[8], wr[8];
#pragma unroll
            for (int i = 0; i < 8; i++) ar[i] = As[k][ty * 8 + i];
#pragma unroll
            for (int j = 0; j < 8; j++) wr[j] = Ws[k][tx * 8 + j];
#pragma unroll
            for (int i = 0; i < 8; i++)
#pragma unroll
                for (int j = 0; j < 8; j++)
                    acc[i][j] = fmaf(ar[i], wr[j], acc[i][j]);
        }
        __syncthreads();
    }

#pragma unroll
    for (int i = 0; i < 8; i++) {
        int r = row0 + ty * 8 + i;
        if (r >= N) break;
#pragma unroll
        for (int j = 0; j < 8; j++) {
            int c = col0 + tx * 8 + j;
            if (c >= F) continue;
            float v = acc[i][j] + bias[c];
            if (Res) v += Res[(size_t)r * ldc + coff + c];
            if (relu) v = fmaxf(v, 0.f);
            C[(size_t)r * ldc + coff + c] = v;
        }
    }
}

// ---------------- flash self-attention, one query row / thread --------------
// qkv layout: [NTOK, 768] row n = l*B+b ; q at +0, k at +256, v at +512, per head h*32
__global__ void __launch_bounds__(128)
attn_kernel(const float* __restrict__ qkv, float* __restrict__ o)
{
    const int bh = blockIdx.y;
    const int b = bh >> 3, h = bh & 7;
    const int qrow = blockIdx.x * 128 + threadIdx.x;
    const bool valid = qrow < NQ;

    float q[32];
    if (valid) {
        const float* qp = qkv + (size_t)(qrow * BATCH + b) * 768 + h * 32;
#pragma unroll
        for (int d = 0; d < 32; d += 4) {
            float4 v = *(const float4*)(qp + d);
            q[d]   = v.x * 0.17677669529663687f;   // 1/sqrt(32)
            q[d+1] = v.y * 0.17677669529663687f;
            q[d+2] = v.z * 0.17677669529663687f;
            q[d+3] = v.w * 0.17677669529663687f;
        }
    }
    float acc[32];
#pragma unroll
    for (int d = 0; d < 32; d++) acc[d] = 0.f;
    float mmax = -1e30f, lsum = 0.f;

    __shared__ float Ks[1024], Vs[1024];

    for (int m0 = 0; m0 < NQ; m0 += 32) {
        int nrows = min(32, NQ - m0);
        {
            int fi = threadIdx.x * 8;
            int r = fi >> 5, d0 = fi & 31;
            if (r < nrows) {
                const float* kp = qkv + (size_t)((m0 + r) * BATCH + b) * 768 + 256 + h * 32 + d0;
                float4 k0 = *(const float4*)kp, k1 = *(const float4*)(kp + 4);
                *(float4*)(Ks + fi) = k0; *(float4*)(Ks + fi + 4) = k1;
                const float* vp = kp + 256;
                float4 v0 = *(const float4*)vp, v1 = *(const float4*)(vp + 4);
                *(float4*)(Vs + fi) = v0; *(float4*)(Vs + fi + 4) = v1;
            }
        }
        __syncthreads();

        if (valid) {
            float s[32];
            float tmax = -1e30f;
            for (int j = 0; j < nrows; j++) {
                const float* kr = Ks + j * 32;
                float d0 = 0.f, d1 = 0.f, d2 = 0.f, d3 = 0.f;
#pragma unroll
                for (int d = 0; d < 32; d += 4) {
                    d0 = fmaf(q[d],   kr[d],   d0);
                    d1 = fmaf(q[d+1], kr[d+1], d1);
                    d2 = fmaf(q[d+2], kr[d+2], d2);
                    d3 = fmaf(q[d+3], kr[d+3], d3);
                }
                s[j] = (d0 + d1) + (d2 + d3);
                tmax = fmaxf(tmax, s[j]);
            }
            float mnew = fmaxf(mmax, tmax);
            float corr = fexp(mmax - mnew);
            lsum *= corr;
#pragma unroll
            for (int d = 0; d < 32; d++) acc[d] *= corr;
            for (int j = 0; j < nrows; j++) {
                float p = fexp(s[j] - mnew);
                lsum += p;
                const float* vr = Vs + j * 32;
#pragma unroll
                for (int d = 0; d < 32; d++)
                    acc[d] = fmaf(p, vr[d], acc[d]);
            }
            mmax = mnew;
        }
        __syncthreads();
    }

    if (valid) {
        float inv = 1.f / lsum;
        float* op = o + (size_t)(qrow * BATCH + b) * DMODEL + h * 32;
#pragma unroll
        for (int d = 0; d < 32; d++) op[d] = acc[d] * inv;
    }
}

// ---------------- LayerNorm, in-place, warp per row (256 cols) --------------
__global__ void ln_kernel(float* __restrict__ x, const float* __restrict__ g,
                          const float* __restrict__ bt, int rows)
{
    int gid = blockIdx.x * blockDim.x + threadIdx.x;
    int r = gid >> 5;
    if (r >= rows) return;
    int lane = gid & 31;
    float* row = x + (size_t)r * 256;
    float v[8]; float s = 0.f;
#pragma unroll
    for (int i = 0; i < 8; i++) { v[i] = row[lane + i * 32]; s += v[i]; }
#pragma unroll
    for (int o = 16; o > 0; o >>= 1) s += __shfl_xor_sync(0xffffffffu, s, o);
    float mean = s * (1.f / 256.f);
    float vs = 0.f;
#pragma unroll
    for (int i = 0; i < 8; i++) { float d = v[i] - mean; vs = fmaf(d, d, vs); }
#pragma unroll
    for (int o = 16; o > 0; o >>= 1) vs += __shfl_xor_sync(0xffffffffu, vs, o);
    float rst = rsqrtf(vs * (1.f / 256.f) + 1e-5f);
#pragma unroll
    for (int i = 0; i < 8; i++) {
        int c = lane + i * 32;
        row[c] = (v[i] - mean) * rst * g[c] + bt[c];
    }
}

// ---------------- deform-attn sampling precompute ---------------------------
// one thread per (token n, head h): softmax 16 weights + 16 sampling coords
__global__ void prep_kernel(const float* __restrict__ off, const float* __restrict__ aw,
                            const float* __restrict__ ref,
                            float* __restrict__ sx, float* __restrict__ sy,
                            float* __restrict__ sw)
{
    int idx = blockIdx.x * blockDim.x + threadIdx.x;
    if (idx >= NTOK * HEADS) return;
    int n = idx >> 3, h = idx & 7;
    const float* op = off + (size_t)n * 256 + h * 32;
    const float* ap = aw  + (size_t)n * 128 + h * 16;
    const float* rp = ref + (size_t)n * 16;   // [NL][4] for token n (q*B+b order matches)

    float a[16]; float mx = -1e30f;
#pragma unroll
    for (int t = 0; t < 16; t++) { a[t] = ap[t]; mx = fmaxf(mx, a[t]); }
    float ssum = 0.f;
#pragma unroll
    for (int t = 0; t < 16; t++) { a[t] = fexp(a[t] - mx); ssum += a[t]; }
    float inv = 1.f / ssum;

    const float Wd[4] = {150.f, 75.f, 38.f, 19.f};
    const float Hh[4] = {100.f, 50.f, 25.f, 13.f};
#pragma unroll
    for (int l = 0; l < 4; l++) {
        float cx = rp[l*4+0], cy = rp[l*4+1], rw = rp[l*4+2], rh = rp[l*4+3];
#pragma unroll
        for (int p = 0; p < 4; p++) {
            float ox = op[(l*4+p)*2+0], oy = op[(l*4+p)*2+1];
            float lx = fmaf(ox * 0.25f * 0.5f, rw, cx);
            float ly = fmaf(oy * 0.25f * 0.5f, rh, cy);
            int o_ = idx * 16 + l * 4 + p;
            sx[o_] = lx * Wd[l] - 0.5f;
            sy[o_] = ly * Hh[l] - 0.5f;
            sw[o_] = a[l*4+p] * inv;
        }
    }
}

// ---------------- deform-attn gather: warp per (token, head), lane = dh -----
__global__ void gather_kernel(const float* __restrict__ val,
                              const float* __restrict__ sx, const float* __restrict__ sy,
                              const float* __restrict__ sw, float* __restrict__ ca)
{
    int gtid = blockIdx.x * blockDim.x + threadIdx.x;
    int wid = gtid >> 5;
    if (wid >= NTOK * HEADS) return;
    int lane = gtid & 31;
    int n = wid >> 3, h = wid & 7;
    int b = n & 7;                    // n = q*B + b, B=8

    const int cW[4] = {150, 75, 38, 19};
    const int cH[4] = {100, 50, 25, 13};
    const int cS[4] = {0, 15000, 18750, 19700};

    const float* vbase = val + (size_t)b * 256 + h * 32 + lane;
    float acc = 0.f;
#pragma unroll
    for (int t = 0; t < 16; t++) {
        int l = t >> 2;
        float x = sx[wid * 16 + t];
        float y = sy[wid * 16 + t];
        float w = sw[wid * 16 + t];
        float xf = floorf(x), yf = floorf(y);
        int x0 = (int)xf, y0 = (int)yf;
        float fx = x - xf, fy = y - yf;
        int W_ = cW[l], H_ = cH[l];
#pragma unroll
        for (int dy = 0; dy < 2; dy++) {
            int yi = y0 + dy;
            if (yi < 0 || yi >= H_) continue;
            float wy = dy ? fy : (1.f - fy);
#pragma unroll
            for (int dx = 0; dx < 2; dx++) {
                int xi = x0 + dx;
                if (xi < 0 || xi >= W_) continue;
                float wx = dx ? fx : (1.f - fx);
                int s = cS[l] + yi * W_ + xi;
                acc = fmaf(w * wy * wx, __ldg(vbase + (size_t)s * (BATCH * 256)), acc);
            }
        }
    }
    ca[(size_t)n * 256 + h * 32 + lane] = acc;
}

// ---------------- launch ----------------------------------------------------
extern "C" void kernel_launch(void* const* d_in, const int* in_sizes, int n_in,
                              void* d_out, int out_size)
{
    (void)in_sizes; (void)n_in; (void)out_size;
    const float* tgt   = (const float*)d_in[0];
    const float* pos   = (const float*)d_in[1];
    const float* ref   = (const float*)d_in[2];
    const float* mem   = (const float*)d_in[3];
    const float* in_w  = (const float*)d_in[6];
    const float* in_b  = (const float*)d_in[7];
    const float* sow   = (const float*)d_in[8];
    const float* sob   = (const float*)d_in[9];
    const float* n1g   = (const float*)d_in[10];
    const float* n1b   = (const float*)d_in[11];
    const float* n2g   = (const float*)d_in[12];
    const float* n2b   = (const float*)d_in[13];
    const float* n3g   = (const float*)d_in[14];
    const float* n3b   = (const float*)d_in[15];
    const float* off_w = (const float*)d_in[16];
    const float* off_b = (const float*)d_in[17];
    const float* aw_w  = (const float*)d_in[18];
    const float* aw_b  = (const float*)d_in[19];
    const float* val_w = (const float*)d_in[20];
    const float* val_b = (const float*)d_in[21];
    const float* cow   = (const float*)d_in[22];
    const float* cob   = (const float*)d_in[23];
    const float* l1w   = (const float*)d_in[24];
    const float* l1b   = (const float*)d_in[25];
    const float* l2w   = (const float*)d_in[26];
    const float* l2b   = (const float*)d_in[27];
    float* out = (float*)d_out;

    float *qkv, *o_, *t2, *offb, *awb, *sx, *sy, *sw, *val, *ca, *t3, *ffn;
    cudaGetSymbolAddress((void**)&qkv,  g_qkv);
    cudaGetSymbolAddress((void**)&o_,   g_o);
    cudaGetSymbolAddress((void**)&t2,   g_t2);
    cudaGetSymbolAddress((void**)&offb, g_off);
    cudaGetSymbolAddress((void**)&awb,  g_aw);
    cudaGetSymbolAddress((void**)&sx,   g_sx);
    cudaGetSymbolAddress((void**)&sy,   g_sy);
    cudaGetSymbolAddress((void**)&sw,   g_sw);
    cudaGetSymbolAddress((void**)&val,  g_val);
    cudaGetSymbolAddress((void**)&ca,   g_ca);
    cudaGetSymbolAddress((void**)&t3,   g_t3);
    cudaGetSymbolAddress((void**)&ffn,  g_ffn);

    auto gg = [](int N, int F) { return dim3((unsigned)((F + 127) / 128), (unsigned)((N + 127) / 128)); };

    // 1-2) QKV projection: q,k from (tgt+pos); v from tgt
    gemm_nt<<<gg(NTOK, 512), 256>>>(tgt, pos, in_w, in_b, nullptr, qkv,
                                    NTOK, 512, 256, 768, 0, 0);
    gemm_nt<<<gg(NTOK, 256), 256>>>(tgt, nullptr, in_w + 512 * 256, in_b + 512, nullptr, qkv,
                                    NTOK, 256, 256, 768, 512, 0);
    // 3) self attention
    attn_kernel<<<dim3((NQ + 127) / 128, BATCH * HEADS), 128>>>(qkv, o_);
    // 4) out proj + residual(tgt), then LN2 -> t2
    gemm_nt<<<gg(NTOK, 256), 256>>>(o_, nullptr, sow, sob, tgt, t2,
                                    NTOK, 256, 256, 256, 0, 0);
    ln_kernel<<<(NTOK * 32 + 255) / 256, 256>>>(t2, n2g, n2b, NTOK);
    // 5) value projection of memory (big GEMM)
    gemm_nt<<<gg(MTOK, 256), 256>>>(mem, nullptr, val_w, val_b, nullptr, val,
                                    MTOK, 256, 256, 256, 0, 0);
    // 6-7) sampling offsets + attention weights from (t2+pos)
    gemm_nt<<<gg(NTOK, 256), 256>>>(t2, pos, off_w, off_b, nullptr, offb,
                                    NTOK, 256, 256, 256, 0, 0);
    gemm_nt<<<gg(NTOK, 128), 256>>>(t2, pos, aw_w, aw_b, nullptr, awb,
                                    NTOK, 128, 256, 128, 0, 0);
    // 8) softmax + sample coords
    prep_kernel<<<(NTOK * HEADS + 255) / 256, 256>>>(offb, awb, ref, sx, sy, sw);
    // 9) bilinear gather
    gather_kernel<<<(NTOK * HEADS * 32 + 255) / 256, 256>>>(val, sx, sy, sw, ca);
    // 10) ca out proj + residual(t2), LN1 -> t3
    gemm_nt<<<gg(NTOK, 256), 256>>>(ca, nullptr, cow, cob, t2, t3,
                                    NTOK, 256, 256, 256, 0, 0);
    ln_kernel<<<(NTOK * 32 + 255) / 256, 256>>>(t3, n1g, n1b, NTOK);
    // 11) FFN
    gemm_nt<<<gg(NTOK, 1024), 256>>>(t3, nullptr, l1w, l1b, nullptr, ffn,
                                     NTOK, 1024, 256, 1024, 0, 1);
    gemm_nt<<<gg(NTOK, 256), 256>>>(ffn, nullptr, l2w, l2b, t3, out,
                                    NTOK, 256, 1024, 256, 0, 0);
    ln_kernel<<<(NTOK * 32 + 255) / 256, 256>>>(out, n3g, n3b, NTOK);
}

// round 5
// speedup vs baseline: 1.5848x; 1.5848x over previous
#include <cuda_runtime.h>
#include <math.h>
#include <stdint.h>

// Problem constants (fixed by the reference)
#define NQ    900
#define BATCH 8
#define NTOK  (NQ*BATCH)        // 7200
#define DMODEL 256
#define HEADS 8
#define DH    32
#define DFF   1024
#define S_TOT 19947
#define MTOK  (S_TOT*BATCH)     // 159576

// ---------------- scratch (static device arrays; no allocation) -------------
__device__ float g_qkv[NTOK*768];
__device__ float g_o  [NTOK*DMODEL];
__device__ float g_t2 [NTOK*DMODEL];
__device__ float g_off[NTOK*256];
__device__ float g_aw [NTOK*128];
__device__ float g_sx [NTOK*HEADS*16];
__device__ float g_sy [NTOK*HEADS*16];
__device__ float g_sw [NTOK*HEADS*16];
__device__ float g_val[(size_t)MTOK*DMODEL];
__device__ float g_ca [NTOK*DMODEL];
__device__ float g_t3 [NTOK*DMODEL];
__device__ float g_ffn[NTOK*DFF];

// ---------------- fast exp (FMA pipe, avoids MUFU bottleneck) ---------------
__device__ __forceinline__ float fexp(float x) {
    x = fmaxf(x, -80.f);
    float t  = x * 1.4426950408889634f;
    float fl = floorf(t);
    float f  = t - fl;
    float p  = 1.5403530e-4f;
    p = fmaf(p, f, 1.3333558e-3f);
    p = fmaf(p, f, 9.6181291e-3f);
    p = fmaf(p, f, 5.5504109e-2f);
    p = fmaf(p, f, 2.4022651e-1f);
    p = fmaf(p, f, 6.9314718e-1f);
    p = fmaf(p, f, 1.0f);
    int ei = (int)fl;
    float sc = __int_as_float((ei + 127) << 23);
    return p * sc;
}

// ---------------- tf32 split helpers ----------------------------------------
__device__ __forceinline__ void splitf(float x, uint32_t& hi, uint32_t& lo) {
    uint32_t h = __float_as_uint(x) & 0xffffe000u;   // exact tf32 value
    hi = h;
    lo = __float_as_uint(x - __uint_as_float(h));    // exact residual
}

#define MMA_TF32(d, a, b)                                                     \
  asm volatile("mma.sync.aligned.m16n8k8.row.col.f32.tf32.tf32.f32 "          \
      "{%0,%1,%2,%3}, {%4,%5,%6,%7}, {%8,%9}, {%0,%1,%2,%3};"                 \
      : "+f"(d[0]), "+f"(d[1]), "+f"(d[2]), "+f"(d[3])                        \
      : "r"(a[0]), "r"(a[1]), "r"(a[2]), "r"(a[3]), "r"(b[0]), "r"(b[1]))

// ---------------- tensor-core NT GEMM:  C[n,f] = A[n,:]·W[f,:] + bias -------
// A row-major [N,K]; W row-major [F,K]. F must be a multiple of 128.
// Compensated tf32 (3-mma split) => ~fp32 accuracy.
// BM=BN=128, BK=16, 256 threads, warp grid 2(m) x 4(n), warp tile 64x32.
__global__ void __launch_bounds__(256)
gemm_tc(const float* __restrict__ A, const float* __restrict__ A2,
        const float* __restrict__ W, const float* __restrict__ bias,
        const float* __restrict__ Res, float* __restrict__ C,
        int N, int F, int K, int ldc, int coff, int relu)
{
    __shared__ float As[2][128][20];   // pad to 20 floats: conflict-free frags
    __shared__ float Bs[2][128][20];

    const int t    = threadIdx.x;
    const int row0 = blockIdx.y * 128, col0 = blockIdx.x * 128;
    const int lrow = t >> 2;           // 0..63
    const int lk   = (t & 3) << 2;     // 0,4,8,12
    const int wid  = t >> 5, lane = t & 31;
    const int wm   = (wid >> 2) * 64;  // 0 or 64
    const int wn   = (wid & 3) * 32;   // 0,32,64,96
    const int g    = lane >> 2, c = lane & 3;

    float acc[4][4][4];
#pragma unroll
    for (int mi = 0; mi < 4; mi++)
#pragma unroll
        for (int nj = 0; nj < 4; nj++)
#pragma unroll
            for (int e = 0; e < 4; e++) acc[mi][nj][e] = 0.f;

    const int nk = K >> 4;

    // --- prologue: tile 0 straight into smem buffer 0 ---
    {
#pragma unroll
        for (int h = 0; h < 2; h++) {
            int r = lrow + h * 64;
            int gr = row0 + r;
            float4 av = make_float4(0.f, 0.f, 0.f, 0.f);
            if (gr < N) {
                av = *(const float4*)(A + (size_t)gr * K + lk);
                if (A2) {
                    float4 p4 = *(const float4*)(A2 + (size_t)gr * K + lk);
                    av.x += p4.x; av.y += p4.y; av.z += p4.z; av.w += p4.w;
                }
            }
            *(float4*)&As[0][r][lk] = av;
            float4 wv = *(const float4*)(W + (size_t)(col0 + r) * K + lk);
            *(float4*)&Bs[0][r][lk] = wv;
        }
    }
    __syncthreads();

    for (int kt = 0; kt < nk; kt++) {
        const int buf = kt & 1;

        // prefetch next tile (global -> regs)
        float4 ra[2], rb[2];
        if (kt + 1 < nk) {
            int kg = (kt + 1) << 4;
#pragma unroll
            for (int h = 0; h < 2; h++) {
                int r = lrow + h * 64;
                int gr = row0 + r;
                ra[h] = make_float4(0.f, 0.f, 0.f, 0.f);
                if (gr < N) {
                    ra[h] = *(const float4*)(A + (size_t)gr * K + kg + lk);
                    if (A2) {
                        float4 p4 = *(const float4*)(A2 + (size_t)gr * K + kg + lk);
                        ra[h].x += p4.x; ra[h].y += p4.y; ra[h].z += p4.z; ra[h].w += p4.w;
                    }
                }
                rb[h] = *(const float4*)(W + (size_t)(col0 + r) * K + kg + lk);
            }
        }

        // compute current tile
#pragma unroll
        for (int k0 = 0; k0 < 16; k0 += 8) {
            uint32_t ah[4][4], al[4][4], bh[4][2], bl[4][2];
#pragma unroll
            for (int mi = 0; mi < 4; mi++) {
                int r = wm + mi * 16 + g;
                splitf(As[buf][r    ][k0 + c    ], ah[mi][0], al[mi][0]);
                splitf(As[buf][r + 8][k0 + c    ], ah[mi][1], al[mi][1]);
                splitf(As[buf][r    ][k0 + c + 4], ah[mi][2], al[mi][2]);
                splitf(As[buf][r + 8][k0 + c + 4], ah[mi][3], al[mi][3]);
            }
#pragma unroll
            for (int nj = 0; nj < 4; nj++) {
                int cn = wn + nj * 8 + g;
                splitf(Bs[buf][cn][k0 + c    ], bh[nj][0], bl[nj][0]);
                splitf(Bs[buf][cn][k0 + c + 4], bh[nj][1], bl[nj][1]);
            }
#pragma unroll
            for (int mi = 0; mi < 4; mi++)
#pragma unroll
                for (int nj = 0; nj < 4; nj++) {
                    MMA_TF32(acc[mi][nj], ah[mi], bh[nj]);
                    MMA_TF32(acc[mi][nj], al[mi], bh[nj]);
                    MMA_TF32(acc[mi][nj], ah[mi], bl[nj]);
                }
        }

        // store prefetched tile into other buffer
        if (kt + 1 < nk) {
            const int nb = buf ^ 1;
#pragma unroll
            for (int h = 0; h < 2; h++) {
                int r = lrow + h * 64;
                *(float4*)&As[nb][r][lk] = ra[h];
                *(float4*)&Bs[nb][r][lk] = rb[h];
            }
        }
        __syncthreads();
    }

    // --- epilogue ---
#pragma unroll
    for (int mi = 0; mi < 4; mi++) {
#pragma unroll
        for (int h = 0; h < 2; h++) {
            int r = row0 + wm + mi * 16 + g + h * 8;
            if (r >= N) continue;
#pragma unroll
            for (int nj = 0; nj < 4; nj++) {
                int cc = col0 + wn + nj * 8 + c * 2;
                float v0 = acc[mi][nj][h * 2 + 0] + bias[cc];
                float v1 = acc[mi][nj][h * 2 + 1] + bias[cc + 1];
                if (Res) {
                    v0 += Res[(size_t)r * ldc + coff + cc];
                    v1 += Res[(size_t)r * ldc + coff + cc + 1];
                }
                if (relu) { v0 = fmaxf(v0, 0.f); v1 = fmaxf(v1, 0.f); }
                float* cp = C + (size_t)r * ldc + coff + cc;
                cp[0] = v0; cp[1] = v1;
            }
        }
    }
}

// ---------------- flash self-attention, one query row / thread --------------
__global__ void __launch_bounds__(128)
attn_kernel(const float* __restrict__ qkv, float* __restrict__ o)
{
    const int bh = blockIdx.y;
    const int b = bh >> 3, h = bh & 7;
    const int qrow = blockIdx.x * 128 + threadIdx.x;
    const bool valid = qrow < NQ;

    float4 q[8];
    if (valid) {
        const float* qp = qkv + (size_t)(qrow * BATCH + b) * 768 + h * 32;
#pragma unroll
        for (int d = 0; d < 8; d++) {
            float4 v = *(const float4*)(qp + d * 4);
            const float s = 0.17677669529663687f;   // 1/sqrt(32)
            q[d].x = v.x * s; q[d].y = v.y * s; q[d].z = v.z * s; q[d].w = v.w * s;
        }
    }
    float4 acc[8];
#pragma unroll
    for (int d = 0; d < 8; d++) acc[d] = make_float4(0.f, 0.f, 0.f, 0.f);
    float mmax = -1e30f, lsum = 0.f;

    __shared__ float Ks[1024], Vs[1024];

    for (int m0 = 0; m0 < NQ; m0 += 32) {
        int nrows = min(32, NQ - m0);
        {
            int fi = threadIdx.x * 8;
            int r = fi >> 5, d0 = fi & 31;
            if (r < nrows) {
                const float* kp = qkv + (size_t)((m0 + r) * BATCH + b) * 768 + 256 + h * 32 + d0;
                *(float4*)(Ks + fi)     = *(const float4*)kp;
                *(float4*)(Ks + fi + 4) = *(const float4*)(kp + 4);
                const float* vp = kp + 256;
                *(float4*)(Vs + fi)     = *(const float4*)vp;
                *(float4*)(Vs + fi + 4) = *(const float4*)(vp + 4);
            }
        }
        __syncthreads();

        if (valid) {
            float s[32];
            float tmax = -1e30f;
            for (int j = 0; j < nrows; j++) {
                const float4* kr = (const float4*)(Ks + j * 32);
                float d0 = 0.f, d1 = 0.f, d2 = 0.f, d3 = 0.f;
#pragma unroll
                for (int d = 0; d < 8; d++) {
                    float4 kv = kr[d];
                    d0 = fmaf(q[d].x, kv.x, d0);
                    d1 = fmaf(q[d].y, kv.y, d1);
                    d2 = fmaf(q[d].z, kv.z, d2);
                    d3 = fmaf(q[d].w, kv.w, d3);
                }
                s[j] = (d0 + d1) + (d2 + d3);
                tmax = fmaxf(tmax, s[j]);
            }
            float mnew = fmaxf(mmax, tmax);
            float corr = fexp(mmax - mnew);
            lsum *= corr;
#pragma unroll
            for (int d = 0; d < 8; d++) {
                acc[d].x *= corr; acc[d].y *= corr; acc[d].z *= corr; acc[d].w *= corr;
            }
            for (int j = 0; j < nrows; j++) {
                float p = fexp(s[j] - mnew);
                lsum += p;
                const float4* vr = (const float4*)(Vs + j * 32);
#pragma unroll
                for (int d = 0; d < 8; d++) {
                    float4 vv = vr[d];
                    acc[d].x = fmaf(p, vv.x, acc[d].x);
                    acc[d].y = fmaf(p, vv.y, acc[d].y);
                    acc[d].z = fmaf(p, vv.z, acc[d].z);
                    acc[d].w = fmaf(p, vv.w, acc[d].w);
                }
            }
            mmax = mnew;
        }
        __syncthreads();
    }

    if (valid) {
        float inv = 1.f / lsum;
        float* op = o + (size_t)(qrow * BATCH + b) * DMODEL + h * 32;
#pragma unroll
        for (int d = 0; d < 8; d++) {
            float4 v;
            v.x = acc[d].x * inv; v.y = acc[d].y * inv;
            v.z = acc[d].z * inv; v.w = acc[d].w * inv;
            *(float4*)(op + d * 4) = v;
        }
    }
}

// ---------------- LayerNorm, in-place, warp per row (256 cols) --------------
__global__ void ln_kernel(float* __restrict__ x, const float* __restrict__ g,
                          const float* __restrict__ bt, int rows)
{
    int gid = blockIdx.x * blockDim.x + threadIdx.x;
    int r = gid >> 5;
    if (r >= rows) return;
    int lane = gid & 31;
    float* row = x + (size_t)r * 256;
    float v[8]; float s = 0.f;
#pragma unroll
    for (int i = 0; i < 8; i++) { v[i] = row[lane + i * 32]; s += v[i]; }
#pragma unroll
    for (int o = 16; o > 0; o >>= 1) s += __shfl_xor_sync(0xffffffffu, s, o);
    float mean = s * (1.f / 256.f);
    float vs = 0.f;
#pragma unroll
    for (int i = 0; i < 8; i++) { float d = v[i] - mean; vs = fmaf(d, d, vs); }
#pragma unroll
    for (int o = 16; o > 0; o >>= 1) vs += __shfl_xor_sync(0xffffffffu, vs, o);
    float rst = rsqrtf(vs * (1.f / 256.f) + 1e-5f);
#pragma unroll
    for (int i = 0; i < 8; i++) {
        int c = lane + i * 32;
        row[c] = (v[i] - mean) * rst * g[c] + bt[c];
    }
}

// ---------------- deform-attn sampling precompute ---------------------------
__global__ void prep_kernel(const float* __restrict__ off, const float* __restrict__ aw,
                            const float* __restrict__ ref,
                            float* __restrict__ sx, float* __restrict__ sy,
                            float* __restrict__ sw)
{
    int idx = blockIdx.x * blockDim.x + threadIdx.x;
    if (idx >= NTOK * HEADS) return;
    int n = idx >> 3, h = idx & 7;
    const float* op = off + (size_t)n * 256 + h * 32;
    const float* ap = aw  + (size_t)n * 128 + h * 16;
    const float* rp = ref + (size_t)n * 16;

    float a[16]; float mx = -1e30f;
#pragma unroll
    for (int t = 0; t < 16; t++) { a[t] = ap[t]; mx = fmaxf(mx, a[t]); }
    float ssum = 0.f;
#pragma unroll
    for (int t = 0; t < 16; t++) { a[t] = fexp(a[t] - mx); ssum += a[t]; }
    float inv = 1.f / ssum;

    const float Wd[4] = {150.f, 75.f, 38.f, 19.f};
    const float Hh[4] = {100.f, 50.f, 25.f, 13.f};
#pragma unroll
    for (int l = 0; l < 4; l++) {
        float cx = rp[l*4+0], cy = rp[l*4+1], rw = rp[l*4+2], rh = rp[l*4+3];
#pragma unroll
        for (int p = 0; p < 4; p++) {
            float ox = op[(l*4+p)*2+0], oy = op[(l*4+p)*2+1];
            float lx = fmaf(ox * 0.25f * 0.5f, rw, cx);
            float ly = fmaf(oy * 0.25f * 0.5f, rh, cy);
            int o_ = idx * 16 + l * 4 + p;
            sx[o_] = lx * Wd[l] - 0.5f;
            sy[o_] = ly * Hh[l] - 0.5f;
            sw[o_] = a[l*4+p] * inv;
        }
    }
}

// ---------------- deform-attn gather: warp per (token, head), lane = dh -----
__global__ void gather_kernel(const float* __restrict__ val,
                              const float* __restrict__ sx, const float* __restrict__ sy,
                              const float* __restrict__ sw, float* __restrict__ ca)
{
    int gtid = blockIdx.x * blockDim.x + threadIdx.x;
    int wid = gtid >> 5;
    if (wid >= NTOK * HEADS) return;
    int lane = gtid & 31;
    int n = wid >> 3, h = wid & 7;
    int b = n & 7;

    const int cW[4] = {150, 75, 38, 19};
    const int cH[4] = {100, 50, 25, 13};
    const int cS[4] = {0, 15000, 18750, 19700};

    const float* vbase = val + (size_t)b * 256 + h * 32 + lane;
    float acc = 0.f;
#pragma unroll
    for (int t = 0; t < 16; t++) {
        int l = t >> 2;
        float x = sx[wid * 16 + t];
        float y = sy[wid * 16 + t];
        float w = sw[wid * 16 + t];
        float xf = floorf(x), yf = floorf(y);
        int x0 = (int)xf, y0 = (int)yf;
        float fx = x - xf, fy = y - yf;
        int W_ = cW[l], H_ = cH[l];
#pragma unroll
        for (int dy = 0; dy < 2; dy++) {
            int yi = y0 + dy;
            if (yi < 0 || yi >= H_) continue;
            float wy = dy ? fy : (1.f - fy);
#pragma unroll
            for (int dx = 0; dx < 2; dx++) {
                int xi = x0 + dx;
                if (xi < 0 || xi >= W_) continue;
                float wx = dx ? fx : (1.f - fx);
                int s = cS[l] + yi * W_ + xi;
                acc = fmaf(w * wy * wx, __ldg(vbase + (size_t)s * (BATCH * 256)), acc);
            }
        }
    }
    ca[(size_t)n * 256 + h * 32 + lane] = acc;
}

// ---------------- launch ----------------------------------------------------
extern "C" void kernel_launch(void* const* d_in, const int* in_sizes, int n_in,
                              void* d_out, int out_size)
{
    (void)in_sizes; (void)n_in; (void)out_size;
    const float* tgt   = (const float*)d_in[0];
    const float* pos   = (const float*)d_in[1];
    const float* ref   = (const float*)d_in[2];
    const float* mem   = (const float*)d_in[3];
    const float* in_w  = (const float*)d_in[6];
    const float* in_b  = (const float*)d_in[7];
    const float* sow   = (const float*)d_in[8];
    const float* sob   = (const float*)d_in[9];
    const float* n1g   = (const float*)d_in[10];
    const float* n1b   = (const float*)d_in[11];
    const float* n2g   = (const float*)d_in[12];
    const float* n2b   = (const float*)d_in[13];
    const float* n3g   = (const float*)d_in[14];
    const float* n3b   = (const float*)d_in[15];
    const float* off_w = (const float*)d_in[16];
    const float* off_b = (const float*)d_in[17];
    const float* aw_w  = (const float*)d_in[18];
    const float* aw_b  = (const float*)d_in[19];
    const float* val_w = (const float*)d_in[20];
    const float* val_b = (const float*)d_in[21];
    const float* cow   = (const float*)d_in[22];
    const float* cob   = (const float*)d_in[23];
    const float* l1w   = (const float*)d_in[24];
    const float* l1b   = (const float*)d_in[25];
    const float* l2w   = (const float*)d_in[26];
    const float* l2b   = (const float*)d_in[27];
    float* out = (float*)d_out;

    float *qkv, *o_, *t2, *offb, *awb, *sx, *sy, *sw, *val, *ca, *t3, *ffn;
    cudaGetSymbolAddress((void**)&qkv,  g_qkv);
    cudaGetSymbolAddress((void**)&o_,   g_o);
    cudaGetSymbolAddress((void**)&t2,   g_t2);
    cudaGetSymbolAddress((void**)&offb, g_off);
    cudaGetSymbolAddress((void**)&awb,  g_aw);
    cudaGetSymbolAddress((void**)&sx,   g_sx);
    cudaGetSymbolAddress((void**)&sy,   g_sy);
    cudaGetSymbolAddress((void**)&sw,   g_sw);
    cudaGetSymbolAddress((void**)&val,  g_val);
    cudaGetSymbolAddress((void**)&ca,   g_ca);
    cudaGetSymbolAddress((void**)&t3,   g_t3);
    cudaGetSymbolAddress((void**)&ffn,  g_ffn);

    auto gg = [](int N, int F) { return dim3((unsigned)(F / 128), (unsigned)((N + 127) / 128)); };

    // 1-2) QKV projection: q,k from (tgt+pos); v from tgt
    gemm_tc<<<gg(NTOK, 512), 256>>>(tgt, pos, in_w, in_b, nullptr, qkv,
                                    NTOK, 512, 256, 768, 0, 0);
    gemm_tc<<<gg(NTOK, 256), 256>>>(tgt, nullptr, in_w + 512 * 256, in_b + 512, nullptr, qkv,
                                    NTOK, 256, 256, 768, 512, 0);
    // 3) self attention
    attn_kernel<<<dim3((NQ + 127) / 128, BATCH * HEADS), 128>>>(qkv, o_);
    // 4) out proj + residual(tgt), then LN2 -> t2
    gemm_tc<<<gg(NTOK, 256), 256>>>(o_, nullptr, sow, sob, tgt, t2,
                                    NTOK, 256, 256, 256, 0, 0);
    ln_kernel<<<(NTOK * 32 + 255) / 256, 256>>>(t2, n2g, n2b, NTOK);
    // 5) value projection of memory (big GEMM)
    gemm_tc<<<gg(MTOK, 256), 256>>>(mem, nullptr, val_w, val_b, nullptr, val,
                                    MTOK, 256, 256, 256, 0, 0);
    // 6-7) sampling offsets + attention weights from (t2+pos)
    gemm_tc<<<gg(NTOK, 256), 256>>>(t2, pos, off_w, off_b, nullptr, offb,
                                    NTOK, 256, 256, 256, 0, 0);
    gemm_tc<<<gg(NTOK, 128), 256>>>(t2, pos, aw_w, aw_b, nullptr, awb,
                                    NTOK, 128, 256, 128, 0, 0);
    // 8) softmax + sample coords
    prep_kernel<<<(NTOK * HEADS + 255) / 256, 256>>>(offb, awb, ref, sx, sy, sw);
    // 9) bilinear gather
    gather_kernel<<<(NTOK * HEADS * 32 + 255) / 256, 256>>>(val, sx, sy, sw, ca);
    // 10) ca out proj + residual(t2), LN1 -> t3
    gemm_tc<<<gg(NTOK, 256), 256>>>(ca, nullptr, cow, cob, t2, t3,
                                    NTOK, 256, 256, 256, 0, 0);
    ln_kernel<<<(NTOK * 32 + 255) / 256, 256>>>(t3, n1g, n1b, NTOK);
    // 11) FFN
    gemm_tc<<<gg(NTOK, 1024), 256>>>(t3, nullptr, l1w, l1b, nullptr, ffn,
                                     NTOK, 1024, 256, 1024, 0, 1);
    gemm_tc<<<gg(NTOK, 256), 256>>>(ffn, nullptr, l2w, l2b, t3, out,
                                    NTOK, 256, 1024, 256, 0, 0);
    ln_kernel<<<(NTOK * 32 + 255) / 256, 256>>>(out, n3g, n3b, NTOK);
}

// round 6
// speedup vs baseline: 1.8311x; 1.1554x over previous
#include <cuda_runtime.h>
#include <cuda_bf16.h>
#include <math.h>
#include <stdint.h>

// Problem constants (fixed by the reference)
#define NQ    900
#define BATCH 8
#define NTOK  (NQ*BATCH)        // 7200
#define DMODEL 256
#define HEADS 8
#define DFF   1024
#define S_TOT 19947
#define MTOK  (S_TOT*BATCH)     // 159576

// ---------------- scratch (static device arrays; no allocation) -------------
__device__ float g_qin[NTOK*DMODEL];
__device__ float g_cain[NTOK*DMODEL];
__device__ float g_qkv[NTOK*768];
__device__ float g_o  [NTOK*DMODEL];
__device__ float g_t2 [NTOK*DMODEL];
__device__ float g_off[NTOK*256];
__device__ float g_aw [NTOK*128];
__device__ float g_sx [NTOK*HEADS*16];
__device__ float g_sy [NTOK*HEADS*16];
__device__ float g_sw [NTOK*HEADS*16];
__device__ float g_val[(size_t)MTOK*DMODEL];
__device__ float g_ca [NTOK*DMODEL];
__device__ float g_t3 [NTOK*DMODEL];
__device__ float g_ffn[NTOK*DFF];

// ---------------- fast exp (FMA pipe, avoids MUFU bottleneck) ---------------
__device__ __forceinline__ float fexp(float x) {
    x = fmaxf(x, -80.f);
    float t  = x * 1.4426950408889634f;
    float fl = floorf(t);
    float f  = t - fl;
    float p  = 1.5403530e-4f;
    p = fmaf(p, f, 1.3333558e-3f);
    p = fmaf(p, f, 9.6181291e-3f);
    p = fmaf(p, f, 5.5504109e-2f);
    p = fmaf(p, f, 2.4022651e-1f);
    p = fmaf(p, f, 6.9314718e-1f);
    p = fmaf(p, f, 1.0f);
    int ei = (int)fl;
    float sc = __int_as_float((ei + 127) << 23);
    return p * sc;
}

// ---------------- bf16 split-pack helpers ------------------------------------
__device__ __forceinline__ void pairsplit(float x, float y, uint32_t& h, uint32_t& l) {
    __nv_bfloat162 hb = __floats2bfloat162_rn(x, y);
    float hx = __bfloat162float(__low2bfloat16(hb));
    float hy = __bfloat162float(__high2bfloat16(hb));
    __nv_bfloat162 lb = __floats2bfloat162_rn(x - hx, y - hy);
    h = *(uint32_t*)&hb;
    l = *(uint32_t*)&lb;
}

#define MMA_BF16(d, a, b)                                                     \
  asm volatile("mma.sync.aligned.m16n8k16.row.col.f32.bf16.bf16.f32 "         \
      "{%0,%1,%2,%3}, {%4,%5,%6,%7}, {%8,%9}, {%0,%1,%2,%3};"                 \
      : "+f"(d[0]), "+f"(d[1]), "+f"(d[2]), "+f"(d[3])                        \
      : "r"(a[0]), "r"(a[1]), "r"(a[2]), "r"(a[3]), "r"(b[0]), "r"(b[1]))

// ---------------- tensor-core NT GEMM:  C[n,f] = A[n,:]·W[f,:] + bias -------
// A row-major [N,K]; W row-major [F,K]. F multiple of 128, K multiple of 16.
// Compensated bf16 (2-way split, 3 mmas) => ~1e-5 relative accuracy.
// BM=BN=128, BK=16, 256 threads, warp grid 2(m) x 4(n), warp tile 64x32.
__global__ void __launch_bounds__(256)
gemm_bf(const float* __restrict__ A, const float* __restrict__ W,
        const float* __restrict__ bias, const float* __restrict__ Res,
        float* __restrict__ C, int N, int F, int K, int ldc, int coff, int relu)
{
    // packed bf16x2 tiles, split hi/lo; 8 words of data per row, stride 12
    // => fragment loads (addr = g*12+c mod 32) are conflict-free.
    __shared__ uint32_t Ah[2][128][12];
    __shared__ uint32_t Al[2][128][12];
    __shared__ uint32_t Bh[2][128][12];
    __shared__ uint32_t Bl[2][128][12];

    const int t    = threadIdx.x;
    const int row0 = blockIdx.y * 128, col0 = blockIdx.x * 128;
    const int lrow = t >> 1;            // 0..127
    const int lh   = t & 1;             // k-half: floats +8*lh, words +4*lh
    const int wid  = t >> 5, lane = t & 31;
    const int wm   = (wid >> 2) * 64;   // 0 or 64
    const int wn   = (wid & 3) * 32;    // 0,32,64,96
    const int g    = lane >> 2, c = lane & 3;

    float acc[4][4][4];
#pragma unroll
    for (int mi = 0; mi < 4; mi++)
#pragma unroll
        for (int nj = 0; nj < 4; nj++)
#pragma unroll
            for (int e = 0; e < 4; e++) acc[mi][nj][e] = 0.f;

    const int nk = K >> 4;

    auto loadA = [&](int kg, float4& u, float4& v) {
        int gr = row0 + lrow;
        if (gr < N) {
            const float* p = A + (size_t)gr * K + kg + lh * 8;
            u = *(const float4*)p;
            v = *(const float4*)(p + 4);
        } else {
            u = make_float4(0.f, 0.f, 0.f, 0.f);
            v = u;
        }
    };
    auto loadB = [&](int kg, float4& u, float4& v) {
        const float* p = W + (size_t)(col0 + lrow) * K + kg + lh * 8;
        u = *(const float4*)p;
        v = *(const float4*)(p + 4);
    };
    auto storeT = [&](uint32_t (*Th)[128][12], uint32_t (*Tl)[128][12],
                      int b, float4 u, float4 v) {
        uint32_t h0, h1, h2, h3, l0, l1, l2, l3;
        pairsplit(u.x, u.y, h0, l0);
        pairsplit(u.z, u.w, h1, l1);
        pairsplit(v.x, v.y, h2, l2);
        pairsplit(v.z, v.w, h3, l3);
        *(uint4*)&Th[b][lrow][lh * 4] = make_uint4(h0, h1, h2, h3);
        *(uint4*)&Tl[b][lrow][lh * 4] = make_uint4(l0, l1, l2, l3);
    };

    // --- prologue: tile 0 -> buffer 0 ---
    {
        float4 au, av, bu, bv;
        loadA(0, au, av);
        loadB(0, bu, bv);
        storeT(Ah, Al, 0, au, av);
        storeT(Bh, Bl, 0, bu, bv);
    }
    __syncthreads();

    for (int kt = 0; kt < nk; kt++) {
        const int buf = kt & 1;
        const bool pf = (kt + 1 < nk);
        float4 au, av, bu, bv;
        if (pf) {
            loadA((kt + 1) << 4, au, av);
            loadB((kt + 1) << 4, bu, bv);
        }

        uint32_t ah[4][4], alr[4][4], bh[4][2], blr[4][2];
#pragma unroll
        for (int mi = 0; mi < 4; mi++) {
            int r = wm + mi * 16 + g;
            ah[mi][0]  = Ah[buf][r    ][c];
            ah[mi][1]  = Ah[buf][r + 8][c];
            ah[mi][2]  = Ah[buf][r    ][c + 4];
            ah[mi][3]  = Ah[buf][r + 8][c + 4];
            alr[mi][0] = Al[buf][r    ][c];
            alr[mi][1] = Al[buf][r + 8][c];
            alr[mi][2] = Al[buf][r    ][c + 4];
            alr[mi][3] = Al[buf][r + 8][c + 4];
        }
#pragma unroll
        for (int nj = 0; nj < 4; nj++) {
            int cn = wn + nj * 8 + g;
            bh[nj][0]  = Bh[buf][cn][c];
            bh[nj][1]  = Bh[buf][cn][c + 4];
            blr[nj][0] = Bl[buf][cn][c];
            blr[nj][1] = Bl[buf][cn][c + 4];
        }
#pragma unroll
        for (int mi = 0; mi < 4; mi++)
#pragma unroll
            for (int nj = 0; nj < 4; nj++) {
                MMA_BF16(acc[mi][nj], ah[mi],  bh[nj]);
                MMA_BF16(acc[mi][nj], alr[mi], bh[nj]);
                MMA_BF16(acc[mi][nj], ah[mi],  blr[nj]);
            }

        if (pf) {
            const int nb = buf ^ 1;
            storeT(Ah, Al, nb, au, av);
            storeT(Bh, Bl, nb, bu, bv);
        }
        __syncthreads();
    }

    // --- epilogue ---
#pragma unroll
    for (int mi = 0; mi < 4; mi++) {
#pragma unroll
        for (int h = 0; h < 2; h++) {
            int r = row0 + wm + mi * 16 + g + h * 8;
            if (r >= N) continue;
#pragma unroll
            for (int nj = 0; nj < 4; nj++) {
                int cc = col0 + wn + nj * 8 + c * 2;
                float v0 = acc[mi][nj][h * 2 + 0] + bias[cc];
                float v1 = acc[mi][nj][h * 2 + 1] + bias[cc + 1];
                if (Res) {
                    v0 += Res[(size_t)r * ldc + coff + cc];
                    v1 += Res[(size_t)r * ldc + coff + cc + 1];
                }
                if (relu) { v0 = fmaxf(v0, 0.f); v1 = fmaxf(v1, 0.f); }
                float* cp = C + (size_t)r * ldc + coff + cc;
                cp[0] = v0; cp[1] = v1;
            }
        }
    }
}

// ---------------- elementwise add (vectorized) -------------------------------
__global__ void add_kernel(const float4* __restrict__ a, const float4* __restrict__ b,
                           float4* __restrict__ o, int n4)
{
    int i = blockIdx.x * blockDim.x + threadIdx.x;
    if (i < n4) {
        float4 x = a[i], y = b[i];
        x.x += y.x; x.y += y.y; x.z += y.z; x.w += y.w;
        o[i] = x;
    }
}

// ---------------- flash self-attention, one query row / thread --------------
__global__ void __launch_bounds__(128)
attn_kernel(const float* __restrict__ qkv, float* __restrict__ o)
{
    const int bh = blockIdx.y;
    const int b = bh >> 3, h = bh & 7;
    const int qrow = blockIdx.x * 128 + threadIdx.x;
    const bool valid = qrow < NQ;

    float4 q[8];
    if (valid) {
        const float* qp = qkv + (size_t)(qrow * BATCH + b) * 768 + h * 32;
#pragma unroll
        for (int d = 0; d < 8; d++) {
            float4 v = *(const float4*)(qp + d * 4);
            const float s = 0.17677669529663687f;   // 1/sqrt(32)
            q[d].x = v.x * s; q[d].y = v.y * s; q[d].z = v.z * s; q[d].w = v.w * s;
        }
    }
    float4 acc[8];
#pragma unroll
    for (int d = 0; d < 8; d++) acc[d] = make_float4(0.f, 0.f, 0.f, 0.f);
    float mmax = -1e30f, lsum = 0.f;

    __shared__ float Ks[1024], Vs[1024];

    for (int m0 = 0; m0 < NQ; m0 += 32) {
        int nrows = min(32, NQ - m0);
        {
            int fi = threadIdx.x * 8;
            int r = fi >> 5, d0 = fi & 31;
            if (r < nrows) {
                const float* kp = qkv + (size_t)((m0 + r) * BATCH + b) * 768 + 256 + h * 32 + d0;
                *(float4*)(Ks + fi)     = *(const float4*)kp;
                *(float4*)(Ks + fi + 4) = *(const float4*)(kp + 4);
                const float* vp = kp + 256;
                *(float4*)(Vs + fi)     = *(const float4*)vp;
                *(float4*)(Vs + fi + 4) = *(const float4*)(vp + 4);
            }
        }
        __syncthreads();

        if (valid) {
            float s[32];
            float tmax = -1e30f;
            for (int j = 0; j < nrows; j++) {
                const float4* kr = (const float4*)(Ks + j * 32);
                float d0 = 0.f, d1 = 0.f, d2 = 0.f, d3 = 0.f;
#pragma unroll
                for (int d = 0; d < 8; d++) {
                    float4 kv = kr[d];
                    d0 = fmaf(q[d].x, kv.x, d0);
                    d1 = fmaf(q[d].y, kv.y, d1);
                    d2 = fmaf(q[d].z, kv.z, d2);
                    d3 = fmaf(q[d].w, kv.w, d3);
                }
                s[j] = (d0 + d1) + (d2 + d3);
                tmax = fmaxf(tmax, s[j]);
            }
            float mnew = fmaxf(mmax, tmax);
            float corr = fexp(mmax - mnew);
            lsum *= corr;
#pragma unroll
            for (int d = 0; d < 8; d++) {
                acc[d].x *= corr; acc[d].y *= corr; acc[d].z *= corr; acc[d].w *= corr;
            }
            for (int j = 0; j < nrows; j++) {
                float p = fexp(s[j] - mnew);
                lsum += p;
                const float4* vr = (const float4*)(Vs + j * 32);
#pragma unroll
                for (int d = 0; d < 8; d++) {
                    float4 vv = vr[d];
                    acc[d].x = fmaf(p, vv.x, acc[d].x);
                    acc[d].y = fmaf(p, vv.y, acc[d].y);
                    acc[d].z = fmaf(p, vv.z, acc[d].z);
                    acc[d].w = fmaf(p, vv.w, acc[d].w);
                }
            }
            mmax = mnew;
        }
        __syncthreads();
    }

    if (valid) {
        float inv = 1.f / lsum;
        float* op = o + (size_t)(qrow * BATCH + b) * DMODEL + h * 32;
#pragma unroll
        for (int d = 0; d < 8; d++) {
            float4 v;
            v.x = acc[d].x * inv; v.y = acc[d].y * inv;
            v.z = acc[d].z * inv; v.w = acc[d].w * inv;
            *(float4*)(op + d * 4) = v;
        }
    }
}

// ---------------- LayerNorm, in-place, warp per row (256 cols) --------------
__global__ void ln_kernel(float* __restrict__ x, const float* __restrict__ g,
                          const float* __restrict__ bt, int rows)
{
    int gid = blockIdx.x * blockDim.x + threadIdx.x;
    int r = gid >> 5;
    if (r >= rows) return;
    int lane = gid & 31;
    float* row = x + (size_t)r * 256;
    float v[8]; float s = 0.f;
#pragma unroll
    for (int i = 0; i < 8; i++) { v[i] = row[lane + i * 32]; s += v[i]; }
#pragma unroll
    for (int o = 16; o > 0; o >>= 1) s += __shfl_xor_sync(0xffffffffu, s, o);
    float mean = s * (1.f / 256.f);
    float vs = 0.f;
#pragma unroll
    for (int i = 0; i < 8; i++) { float d = v[i] - mean; vs = fmaf(d, d, vs); }
#pragma unroll
    for (int o = 16; o > 0; o >>= 1) vs += __shfl_xor_sync(0xffffffffu, vs, o);
    float rst = rsqrtf(vs * (1.f / 256.f) + 1e-5f);
#pragma unroll
    for (int i = 0; i < 8; i++) {
        int c = lane + i * 32;
        row[c] = (v[i] - mean) * rst * g[c] + bt[c];
    }
}

// ---------------- deform-attn sampling precompute ---------------------------
__global__ void prep_kernel(const float* __restrict__ off, const float* __restrict__ aw,
                            const float* __restrict__ ref,
                            float* __restrict__ sx, float* __restrict__ sy,
                            float* __restrict__ sw)
{
    int idx = blockIdx.x * blockDim.x + threadIdx.x;
    if (idx >= NTOK * HEADS) return;
    int n = idx >> 3, h = idx & 7;
    const float* op = off + (size_t)n * 256 + h * 32;
    const float* ap = aw  + (size_t)n * 128 + h * 16;
    const float* rp = ref + (size_t)n * 16;

    float a[16]; float mx = -1e30f;
#pragma unroll
    for (int t = 0; t < 16; t++) { a[t] = ap[t]; mx = fmaxf(mx, a[t]); }
    float ssum = 0.f;
#pragma unroll
    for (int t = 0; t < 16; t++) { a[t] = fexp(a[t] - mx); ssum += a[t]; }
    float inv = 1.f / ssum;

    const float Wd[4] = {150.f, 75.f, 38.f, 19.f};
    const float Hh[4] = {100.f, 50.f, 25.f, 13.f};
#pragma unroll
    for (int l = 0; l < 4; l++) {
        float cx = rp[l*4+0], cy = rp[l*4+1], rw = rp[l*4+2], rh = rp[l*4+3];
#pragma unroll
        for (int p = 0; p < 4; p++) {
            float ox = op[(l*4+p)*2+0], oy = op[(l*4+p)*2+1];
            float lx = fmaf(ox * 0.25f * 0.5f, rw, cx);
            float ly = fmaf(oy * 0.25f * 0.5f, rh, cy);
            int o_ = idx * 16 + l * 4 + p;
            sx[o_] = lx * Wd[l] - 0.5f;
            sy[o_] = ly * Hh[l] - 0.5f;
            sw[o_] = a[l*4+p] * inv;
        }
    }
}

// ---------------- deform-attn gather: warp per (token, head), lane = dh -----
__global__ void gather_kernel(const float* __restrict__ val,
                              const float* __restrict__ sx, const float* __restrict__ sy,
                              const float* __restrict__ sw, float* __restrict__ ca)
{
    int gtid = blockIdx.x * blockDim.x + threadIdx.x;
    int wid = gtid >> 5;
    if (wid >= NTOK * HEADS) return;
    int lane = gtid & 31;
    int n = wid >> 3, h = wid & 7;
    int b = n & 7;

    const int cW[4] = {150, 75, 38, 19};
    const int cH[4] = {100, 50, 25, 13};
    const int cS[4] = {0, 15000, 18750, 19700};

    const float* vbase = val + (size_t)b * 256 + h * 32 + lane;
    float acc = 0.f;
#pragma unroll
    for (int t = 0; t < 16; t++) {
        int l = t >> 2;
        float x = sx[wid * 16 + t];
        float y = sy[wid * 16 + t];
        float w = sw[wid * 16 + t];
        float xf = floorf(x), yf = floorf(y);
        int x0 = (int)xf, y0 = (int)yf;
        float fx = x - xf, fy = y - yf;
        int W_ = cW[l], H_ = cH[l];
#pragma unroll
        for (int dy = 0; dy < 2; dy++) {
            int yi = y0 + dy;
            if (yi < 0 || yi >= H_) continue;
            float wy = dy ? fy : (1.f - fy);
#pragma unroll
            for (int dx = 0; dx < 2; dx++) {
                int xi = x0 + dx;
                if (xi < 0 || xi >= W_) continue;
                float wx = dx ? fx : (1.f - fx);
                int s = cS[l] + yi * W_ + xi;
                acc = fmaf(w * wy * wx, __ldg(vbase + (size_t)s * (BATCH * 256)), acc);
            }
        }
    }
    ca[(size_t)n * 256 + h * 32 + lane] = acc;
}

// ---------------- launch ----------------------------------------------------
extern "C" void kernel_launch(void* const* d_in, const int* in_sizes, int n_in,
                              void* d_out, int out_size)
{
    (void)in_sizes; (void)n_in; (void)out_size;
    const float* tgt   = (const float*)d_in[0];
    const float* pos   = (const float*)d_in[1];
    const float* ref   = (const float*)d_in[2];
    const float* mem   = (const float*)d_in[3];
    const float* in_w  = (const float*)d_in[6];
    const float* in_b  = (const float*)d_in[7];
    const float* sow   = (const float*)d_in[8];
    const float* sob   = (const float*)d_in[9];
    const float* n1g   = (const float*)d_in[10];
    const float* n1b   = (const float*)d_in[11];
    const float* n2g   = (const float*)d_in[12];
    const float* n2b   = (const float*)d_in[13];
    const float* n3g   = (const float*)d_in[14];
    const float* n3b   = (const float*)d_in[15];
    const float* off_w = (const float*)d_in[16];
    const float* off_b = (const float*)d_in[17];
    const float* aw_w  = (const float*)d_in[18];
    const float* aw_b  = (const float*)d_in[19];
    const float* val_w = (const float*)d_in[20];
    const float* val_b = (const float*)d_in[21];
    const float* cow   = (const float*)d_in[22];
    const float* cob   = (const float*)d_in[23];
    const float* l1w   = (const float*)d_in[24];
    const float* l1b   = (const float*)d_in[25];
    const float* l2w   = (const float*)d_in[26];
    const float* l2b   = (const float*)d_in[27];
    float* out = (float*)d_out;

    float *qin, *cain, *qkv, *o_, *t2, *offb, *awb, *sx, *sy, *sw, *val, *ca, *t3, *ffn;
    cudaGetSymbolAddress((void**)&qin,  g_qin);
    cudaGetSymbolAddress((void**)&cain, g_cain);
    cudaGetSymbolAddress((void**)&qkv,  g_qkv);
    cudaGetSymbolAddress((void**)&o_,   g_o);
    cudaGetSymbolAddress((void**)&t2,   g_t2);
    cudaGetSymbolAddress((void**)&offb, g_off);
    cudaGetSymbolAddress((void**)&awb,  g_aw);
    cudaGetSymbolAddress((void**)&sx,   g_sx);
    cudaGetSymbolAddress((void**)&sy,   g_sy);
    cudaGetSymbolAddress((void**)&sw,   g_sw);
    cudaGetSymbolAddress((void**)&val,  g_val);
    cudaGetSymbolAddress((void**)&ca,   g_ca);
    cudaGetSymbolAddress((void**)&t3,   g_t3);
    cudaGetSymbolAddress((void**)&ffn,  g_ffn);

    auto gg = [](int N, int F) { return dim3((unsigned)(F / 128), (unsigned)((N + 127) / 128)); };
    const int n4 = NTOK * DMODEL / 4;

    // 0) value projection of memory (biggest GEMM) — independent, launch first
    gemm_bf<<<gg(MTOK, 256), 256>>>(mem, val_w, val_b, nullptr, val,
                                    MTOK, 256, 256, 256, 0, 0);
    // 1) qin = tgt + pos
    add_kernel<<<(n4 + 255) / 256, 256>>>((const float4*)tgt, (const float4*)pos,
                                          (float4*)qin, n4);
    // 2-3) QKV projection: q,k from qin; v from tgt
    gemm_bf<<<gg(NTOK, 512), 256>>>(qin, in_w, in_b, nullptr, qkv,
                                    NTOK, 512, 256, 768, 0, 0);
    gemm_bf<<<gg(NTOK, 256), 256>>>(tgt, in_w + 512 * 256, in_b + 512, nullptr, qkv,
                                    NTOK, 256, 256, 768, 512, 0);
    // 4) self attention
    attn_kernel<<<dim3((NQ + 127) / 128, BATCH * HEADS), 128>>>(qkv, o_);
    // 5) out proj + residual(tgt), then LN2 -> t2
    gemm_bf<<<gg(NTOK, 256), 256>>>(o_, sow, sob, tgt, t2,
                                    NTOK, 256, 256, 256, 0, 0);
    ln_kernel<<<(NTOK * 32 + 255) / 256, 256>>>(t2, n2g, n2b, NTOK);
    // 6) cain = t2 + pos
    add_kernel<<<(n4 + 255) / 256, 256>>>((const float4*)t2, (const float4*)pos,
                                          (float4*)cain, n4);
    // 7-8) sampling offsets + attention weights from cain
    gemm_bf<<<gg(NTOK, 256), 256>>>(cain, off_w, off_b, nullptr, offb,
                                    NTOK, 256, 256, 256, 0, 0);
    gemm_bf<<<gg(NTOK, 128), 256>>>(cain, aw_w, aw_b, nullptr, awb,
                                    NTOK, 128, 256, 128, 0, 0);
    // 9) softmax + sample coords
    prep_kernel<<<(NTOK * HEADS + 255) / 256, 256>>>(offb, awb, ref, sx, sy, sw);
    // 10) bilinear gather
    gather_kernel<<<(NTOK * HEADS * 32 + 255) / 256, 256>>>(val, sx, sy, sw, ca);
    // 11) ca out proj + residual(t2), LN1 -> t3
    gemm_bf<<<gg(NTOK, 256), 256>>>(ca, cow, cob, t2, t3,
                                    NTOK, 256, 256, 256, 0, 0);
    ln_kernel<<<(NTOK * 32 + 255) / 256, 256>>>(t3, n1g, n1b, NTOK);
    // 12) FFN
    gemm_bf<<<gg(NTOK, 1024), 256>>>(t3, l1w, l1b, nullptr, ffn,
                                     NTOK, 1024, 256, 1024, 0, 1);
    gemm_bf<<<gg(NTOK, 256), 256>>>(ffn, l2w, l2b, t3, out,
                                    NTOK, 256, 1024, 256, 0, 0);
    ln_kernel<<<(NTOK * 32 + 255) / 256, 256>>>(out, n3g, n3b, NTOK);
}

// round 7
// speedup vs baseline: 1.9590x; 1.0699x over previous
#include <cuda_runtime.h>
#include <cuda_bf16.h>
#include <math.h>
#include <stdint.h>

// Problem constants (fixed by the reference)
#define NQ    900
#define BATCH 8
#define NTOK  (NQ*BATCH)        // 7200
#define DMODEL 256
#define HEADS 8
#define DFF   1024
#define S_TOT 19947
#define MTOK  (S_TOT*BATCH)     // 159576

// ---------------- scratch (static device arrays; no allocation) -------------
__device__ float g_qin[NTOK*DMODEL];
__device__ float g_cain[NTOK*DMODEL];
__device__ float g_qkv[NTOK*768];
__device__ float g_o  [NTOK*DMODEL];
__device__ float g_t2 [NTOK*DMODEL];
__device__ float g_off[NTOK*256];
__device__ float g_aw [NTOK*128];
__device__ float g_sx [NTOK*HEADS*16];
__device__ float g_sy [NTOK*HEADS*16];
__device__ float g_sw [NTOK*HEADS*16];
__device__ float g_val[(size_t)MTOK*DMODEL];
__device__ float g_ca [NTOK*DMODEL];
__device__ float g_t3 [NTOK*DMODEL];
__device__ float g_ffn[NTOK*DFF];

// ---------------- fast exp (FMA pipe, avoids MUFU bottleneck) ---------------
__device__ __forceinline__ float fexp(float x) {
    x = fmaxf(x, -80.f);
    float t  = x * 1.4426950408889634f;
    float fl = floorf(t);
    float f  = t - fl;
    float p  = 1.5403530e-4f;
    p = fmaf(p, f, 1.3333558e-3f);
    p = fmaf(p, f, 9.6181291e-3f);
    p = fmaf(p, f, 5.5504109e-2f);
    p = fmaf(p, f, 2.4022651e-1f);
    p = fmaf(p, f, 6.9314718e-1f);
    p = fmaf(p, f, 1.0f);
    int ei = (int)fl;
    float sc = __int_as_float((ei + 127) << 23);
    return p * sc;
}

// ---------------- bf16 split-pack helpers ------------------------------------
__device__ __forceinline__ void pairsplit(float x, float y, uint32_t& h, uint32_t& l) {
    __nv_bfloat162 hb = __floats2bfloat162_rn(x, y);
    float hx = __bfloat162float(__low2bfloat16(hb));
    float hy = __bfloat162float(__high2bfloat16(hb));
    __nv_bfloat162 lb = __floats2bfloat162_rn(x - hx, y - hy);
    h = *(uint32_t*)&hb;
    l = *(uint32_t*)&lb;
}

#define MMA_BF16(d, a, b)                                                     \
  asm volatile("mma.sync.aligned.m16n8k16.row.col.f32.bf16.bf16.f32 "         \
      "{%0,%1,%2,%3}, {%4,%5,%6,%7}, {%8,%9}, {%0,%1,%2,%3};"                 \
      : "+f"(d[0]), "+f"(d[1]), "+f"(d[2]), "+f"(d[3])                        \
      : "r"(a[0]), "r"(a[1]), "r"(a[2]), "r"(a[3]), "r"(b[0]), "r"(b[1]))

#define LDSM4(R, addr)                                                        \
  asm volatile("ldmatrix.sync.aligned.m8n8.x4.shared.b16 {%0,%1,%2,%3}, [%4];"\
      : "=r"((R)[0]), "=r"((R)[1]), "=r"((R)[2]), "=r"((R)[3]) : "r"(addr))

// ---------------- tensor-core NT GEMM:  C[n,f] = A[n,:]·W[f,:] + bias -------
// A row-major [N,K]; W row-major [F,K]. F multiple of 128, K multiple of 16.
// Compensated bf16 (2-way split, 3 mmas) => ~1e-5 relative accuracy.
// BM=BN=128, BK=16, 256 threads, warp grid 2(m) x 4(n), warp tile 64x32.
// Fragments loaded via ldmatrix.x4 (conflict-free on the 48B-stride layout).
__global__ void __launch_bounds__(256)
gemm_bf(const float* __restrict__ A, const float* __restrict__ W,
        const float* __restrict__ bias, const float* __restrict__ Res,
        float* __restrict__ C, int N, int F, int K, int ldc, int coff, int relu)
{
    // packed bf16x2 tiles, split hi/lo; 8 words of data per row, stride 12.
    __shared__ uint32_t Ah[2][128][12];
    __shared__ uint32_t Al[2][128][12];
    __shared__ uint32_t Bh[2][128][12];
    __shared__ uint32_t Bl[2][128][12];
    const uint32_t BUFB = 128 * 12 * 4;   // bytes per buffer

    const int t    = threadIdx.x;
    const int row0 = blockIdx.y * 128, col0 = blockIdx.x * 128;
    const int lrow = t >> 1;            // 0..127
    const int lh   = t & 1;             // k-half: floats +8*lh, words +4*lh
    const int wid  = t >> 5, lane = t & 31;
    const int wm   = (wid >> 2) * 64;   // 0 or 64
    const int wn   = (wid & 3) * 32;    // 0,32,64,96
    const int g    = lane >> 2, c = lane & 3;

    // ldmatrix per-lane base addresses (buffer 0)
    const uint32_t bAh = (uint32_t)__cvta_generic_to_shared(&Ah[0][0][0]);
    const uint32_t bAl = (uint32_t)__cvta_generic_to_shared(&Al[0][0][0]);
    const uint32_t bBh = (uint32_t)__cvta_generic_to_shared(&Bh[0][0][0]);
    const uint32_t bBl = (uint32_t)__cvta_generic_to_shared(&Bl[0][0][0]);
    const int arow  = lane & 15;             // A: rows 0..15 of the 16x16 frag
    const int akoff = (lane >> 4) * 16;      // +16B for k8..15 half
    uint32_t aAh[4], aAl[4];
#pragma unroll
    for (int mi = 0; mi < 4; mi++) {
        uint32_t off = (uint32_t)((wm + mi * 16 + arow) * 48 + akoff);
        aAh[mi] = bAh + off;
        aAl[mi] = bAl + off;
    }
    const int brow  = (lane & 7) + ((lane >> 4) << 3);  // n row within 16
    const int bkoff = ((lane >> 3) & 1) * 16;           // k-half byte offset
    uint32_t aBh[2], aBl[2];
#pragma unroll
    for (int njp = 0; njp < 2; njp++) {
        uint32_t off = (uint32_t)((wn + njp * 16 + brow) * 48 + bkoff);
        aBh[njp] = bBh + off;
        aBl[njp] = bBl + off;
    }

    float acc[4][4][4];
#pragma unroll
    for (int mi = 0; mi < 4; mi++)
#pragma unroll
        for (int nj = 0; nj < 4; nj++)
#pragma unroll
            for (int e = 0; e < 4; e++) acc[mi][nj][e] = 0.f;

    const int nk = K >> 4;

    auto loadA = [&](int kg, float4& u, float4& v) {
        int gr = row0 + lrow;
        if (gr < N) {
            const float* p = A + (size_t)gr * K + kg + lh * 8;
            u = *(const float4*)p;
            v = *(const float4*)(p + 4);
        } else {
            u = make_float4(0.f, 0.f, 0.f, 0.f);
            v = u;
        }
    };
    auto loadB = [&](int kg, float4& u, float4& v) {
        const float* p = W + (size_t)(col0 + lrow) * K + kg + lh * 8;
        u = *(const float4*)p;
        v = *(const float4*)(p + 4);
    };
    auto storeT = [&](uint32_t (*Th)[128][12], uint32_t (*Tl)[128][12],
                      int b, float4 u, float4 v) {
        uint32_t h0, h1, h2, h3, l0, l1, l2, l3;
        pairsplit(u.x, u.y, h0, l0);
        pairsplit(u.z, u.w, h1, l1);
        pairsplit(v.x, v.y, h2, l2);
        pairsplit(v.z, v.w, h3, l3);
        *(uint4*)&Th[b][lrow][lh * 4] = make_uint4(h0, h1, h2, h3);
        *(uint4*)&Tl[b][lrow][lh * 4] = make_uint4(l0, l1, l2, l3);
    };

    // --- prologue: tile 0 -> buffer 0 ---
    {
        float4 au, av, bu, bv;
        loadA(0, au, av);
        loadB(0, bu, bv);
        storeT(Ah, Al, 0, au, av);
        storeT(Bh, Bl, 0, bu, bv);
    }
    __syncthreads();

    for (int kt = 0; kt < nk; kt++) {
        const uint32_t bo = (kt & 1) ? BUFB : 0u;
        const bool pf = (kt + 1 < nk);
        float4 au, av, bu, bv;
        if (pf) {
            loadA((kt + 1) << 4, au, av);
            loadB((kt + 1) << 4, bu, bv);
        }

        uint32_t ah[4][4], alr[4][4], bh[4][2], blr[4][2];
#pragma unroll
        for (int mi = 0; mi < 4; mi++) {
            LDSM4(ah[mi],  aAh[mi] + bo);
            LDSM4(alr[mi], aAl[mi] + bo);
        }
#pragma unroll
        for (int njp = 0; njp < 2; njp++) {
            uint32_t bt[4], bt2[4];
            LDSM4(bt,  aBh[njp] + bo);
            LDSM4(bt2, aBl[njp] + bo);
            bh[njp*2  ][0] = bt[0];  bh[njp*2  ][1] = bt[1];
            bh[njp*2+1][0] = bt[2];  bh[njp*2+1][1] = bt[3];
            blr[njp*2  ][0] = bt2[0]; blr[njp*2  ][1] = bt2[1];
            blr[njp*2+1][0] = bt2[2]; blr[njp*2+1][1] = bt2[3];
        }
#pragma unroll
        for (int mi = 0; mi < 4; mi++)
#pragma unroll
            for (int nj = 0; nj < 4; nj++) {
                MMA_BF16(acc[mi][nj], ah[mi],  bh[nj]);
                MMA_BF16(acc[mi][nj], alr[mi], bh[nj]);
                MMA_BF16(acc[mi][nj], ah[mi],  blr[nj]);
            }

        if (pf) {
            const int nb = (kt & 1) ^ 1;
            storeT(Ah, Al, nb, au, av);
            storeT(Bh, Bl, nb, bu, bv);
        }
        __syncthreads();
    }

    // --- epilogue ---
#pragma unroll
    for (int mi = 0; mi < 4; mi++) {
#pragma unroll
        for (int h = 0; h < 2; h++) {
            int r = row0 + wm + mi * 16 + g + h * 8;
            if (r >= N) continue;
#pragma unroll
            for (int nj = 0; nj < 4; nj++) {
                int cc = col0 + wn + nj * 8 + c * 2;
                float v0 = acc[mi][nj][h * 2 + 0] + bias[cc];
                float v1 = acc[mi][nj][h * 2 + 1] + bias[cc + 1];
                if (Res) {
                    v0 += Res[(size_t)r * ldc + coff + cc];
                    v1 += Res[(size_t)r * ldc + coff + cc + 1];
                }
                if (relu) { v0 = fmaxf(v0, 0.f); v1 = fmaxf(v1, 0.f); }
                float* cp = C + (size_t)r * ldc + coff + cc;
                cp[0] = v0; cp[1] = v1;
            }
        }
    }
}

// ---------------- elementwise add (vectorized) -------------------------------
__global__ void add_kernel(const float4* __restrict__ a, const float4* __restrict__ b,
                           float4* __restrict__ o, int n4)
{
    int i = blockIdx.x * blockDim.x + threadIdx.x;
    if (i < n4) {
        float4 x = a[i], y = b[i];
        x.x += y.x; x.y += y.y; x.z += y.z; x.w += y.w;
        o[i] = x;
    }
}

// ---------------- flash self-attention, one query row / thread --------------
__global__ void __launch_bounds__(128)
attn_kernel(const float* __restrict__ qkv, float* __restrict__ o)
{
    const int bh = blockIdx.y;
    const int b = bh >> 3, h = bh & 7;
    const int qrow = blockIdx.x * 128 + threadIdx.x;
    const bool valid = qrow < NQ;

    float4 q[8];
    if (valid) {
        const float* qp = qkv + (size_t)(qrow * BATCH + b) * 768 + h * 32;
#pragma unroll
        for (int d = 0; d < 8; d++) {
            float4 v = *(const float4*)(qp + d * 4);
            const float s = 0.17677669529663687f;   // 1/sqrt(32)
            q[d].x = v.x * s; q[d].y = v.y * s; q[d].z = v.z * s; q[d].w = v.w * s;
        }
    }
    float4 acc[8];
#pragma unroll
    for (int d = 0; d < 8; d++) acc[d] = make_float4(0.f, 0.f, 0.f, 0.f);
    float mmax = -1e30f, lsum = 0.f;

    __shared__ float Ks[1024], Vs[1024];

    for (int m0 = 0; m0 < NQ; m0 += 32) {
        int nrows = min(32, NQ - m0);
        {
            int fi = threadIdx.x * 8;
            int r = fi >> 5, d0 = fi & 31;
            if (r < nrows) {
                const float* kp = qkv + (size_t)((m0 + r) * BATCH + b) * 768 + 256 + h * 32 + d0;
                *(float4*)(Ks + fi)     = *(const float4*)kp;
                *(float4*)(Ks + fi + 4) = *(const float4*)(kp + 4);
                const float* vp = kp + 256;
                *(float4*)(Vs + fi)     = *(const float4*)vp;
                *(float4*)(Vs + fi + 4) = *(const float4*)(vp + 4);
            }
        }
        __syncthreads();

        if (valid) {
            float s[32];
            float tmax = -1e30f;
            for (int j = 0; j < nrows; j++) {
                const float4* kr = (const float4*)(Ks + j * 32);
                float d0 = 0.f, d1 = 0.f, d2 = 0.f, d3 = 0.f;
#pragma unroll
                for (int d = 0; d < 8; d++) {
                    float4 kv = kr[d];
                    d0 = fmaf(q[d].x, kv.x, d0);
                    d1 = fmaf(q[d].y, kv.y, d1);
                    d2 = fmaf(q[d].z, kv.z, d2);
                    d3 = fmaf(q[d].w, kv.w, d3);
                }
                s[j] = (d0 + d1) + (d2 + d3);
                tmax = fmaxf(tmax, s[j]);
            }
            float mnew = fmaxf(mmax, tmax);
            float corr = fexp(mmax - mnew);
            lsum *= corr;
#pragma unroll
            for (int d = 0; d < 8; d++) {
                acc[d].x *= corr; acc[d].y *= corr; acc[d].z *= corr; acc[d].w *= corr;
            }
            for (int j = 0; j < nrows; j++) {
                float p = fexp(s[j] - mnew);
                lsum += p;
                const float4* vr = (const float4*)(Vs + j * 32);
#pragma unroll
                for (int d = 0; d < 8; d++) {
                    float4 vv = vr[d];
                    acc[d].x = fmaf(p, vv.x, acc[d].x);
                    acc[d].y = fmaf(p, vv.y, acc[d].y);
                    acc[d].z = fmaf(p, vv.z, acc[d].z);
                    acc[d].w = fmaf(p, vv.w, acc[d].w);
                }
            }
            mmax = mnew;
        }
        __syncthreads();
    }

    if (valid) {
        float inv = 1.f / lsum;
        float* op = o + (size_t)(qrow * BATCH + b) * DMODEL + h * 32;
#pragma unroll
        for (int d = 0; d < 8; d++) {
            float4 v;
            v.x = acc[d].x * inv; v.y = acc[d].y * inv;
            v.z = acc[d].z * inv; v.w = acc[d].w * inv;
            *(float4*)(op + d * 4) = v;
        }
    }
}

// ---------------- LayerNorm, in-place, warp per row (256 cols) --------------
__global__ void ln_kernel(float* __restrict__ x, const float* __restrict__ g,
                          const float* __restrict__ bt, int rows)
{
    int gid = blockIdx.x * blockDim.x + threadIdx.x;
    int r = gid >> 5;
    if (r >= rows) return;
    int lane = gid & 31;
    float* row = x + (size_t)r * 256;
    float v[8]; float s = 0.f;
#pragma unroll
    for (int i = 0; i < 8; i++) { v[i] = row[lane + i * 32]; s += v[i]; }
#pragma unroll
    for (int o = 16; o > 0; o >>= 1) s += __shfl_xor_sync(0xffffffffu, s, o);
    float mean = s * (1.f / 256.f);
    float vs = 0.f;
#pragma unroll
    for (int i = 0; i < 8; i++) { float d = v[i] - mean; vs = fmaf(d, d, vs); }
#pragma unroll
    for (int o = 16; o > 0; o >>= 1) vs += __shfl_xor_sync(0xffffffffu, vs, o);
    float rst = rsqrtf(vs * (1.f / 256.f) + 1e-5f);
#pragma unroll
    for (int i = 0; i < 8; i++) {
        int c = lane + i * 32;
        row[c] = (v[i] - mean) * rst * g[c] + bt[c];
    }
}

// ---------------- deform-attn sampling precompute ---------------------------
__global__ void prep_kernel(const float* __restrict__ off, const float* __restrict__ aw,
                            const float* __restrict__ ref,
                            float* __restrict__ sx, float* __restrict__ sy,
                            float* __restrict__ sw)
{
    int idx = blockIdx.x * blockDim.x + threadIdx.x;
    if (idx >= NTOK * HEADS) return;
    int n = idx >> 3, h = idx & 7;
    const float* op = off + (size_t)n * 256 + h * 32;
    const float* ap = aw  + (size_t)n * 128 + h * 16;
    const float* rp = ref + (size_t)n * 16;

    float a[16]; float mx = -1e30f;
#pragma unroll
    for (int t = 0; t < 16; t++) { a[t] = ap[t]; mx = fmaxf(mx, a[t]); }
    float ssum = 0.f;
#pragma unroll
    for (int t = 0; t < 16; t++) { a[t] = fexp(a[t] - mx); ssum += a[t]; }
    float inv = 1.f / ssum;

    const float Wd[4] = {150.f, 75.f, 38.f, 19.f};
    const float Hh[4] = {100.f, 50.f, 25.f, 13.f};
#pragma unroll
    for (int l = 0; l < 4; l++) {
        float cx = rp[l*4+0], cy = rp[l*4+1], rw = rp[l*4+2], rh = rp[l*4+3];
#pragma unroll
        for (int p = 0; p < 4; p++) {
            float ox = op[(l*4+p)*2+0], oy = op[(l*4+p)*2+1];
            float lx = fmaf(ox * 0.25f * 0.5f, rw, cx);
            float ly = fmaf(oy * 0.25f * 0.5f, rh, cy);
            int o_ = idx * 16 + l * 4 + p;
            sx[o_] = lx * Wd[l] - 0.5f;
            sy[o_] = ly * Hh[l] - 0.5f;
            sw[o_] = a[l*4+p] * inv;
        }
    }
}

// ---------------- deform-attn gather: warp per (token, head), lane = dh -----
__global__ void gather_kernel(const float* __restrict__ val,
                              const float* __restrict__ sx, const float* __restrict__ sy,
                              const float* __restrict__ sw, float* __restrict__ ca)
{
    int gtid = blockIdx.x * blockDim.x + threadIdx.x;
    int wid = gtid >> 5;
    if (wid >= NTOK * HEADS) return;
    int lane = gtid & 31;
    int n = wid >> 3, h = wid & 7;
    int b = n & 7;

    const int cW[4] = {150, 75, 38, 19};
    const int cH[4] = {100, 50, 25, 13};
    const int cS[4] = {0, 15000, 18750, 19700};

    const float* vbase = val + (size_t)b * 256 + h * 32 + lane;
    float acc = 0.f;
#pragma unroll
    for (int t = 0; t < 16; t++) {
        int l = t >> 2;
        float x = sx[wid * 16 + t];
        float y = sy[wid * 16 + t];
        float w = sw[wid * 16 + t];
        float xf = floorf(x), yf = floorf(y);
        int x0 = (int)xf, y0 = (int)yf;
        float fx = x - xf, fy = y - yf;
        int W_ = cW[l], H_ = cH[l];
#pragma unroll
        for (int dy = 0; dy < 2; dy++) {
            int yi = y0 + dy;
            if (yi < 0 || yi >= H_) continue;
            float wy = dy ? fy : (1.f - fy);
#pragma unroll
            for (int dx = 0; dx < 2; dx++) {
                int xi = x0 + dx;
                if (xi < 0 || xi >= W_) continue;
                float wx = dx ? fx : (1.f - fx);
                int s = cS[l] + yi * W_ + xi;
                acc = fmaf(w * wy * wx, __ldg(vbase + (size_t)s * (BATCH * 256)), acc);
            }
        }
    }
    ca[(size_t)n * 256 + h * 32 + lane] = acc;
}

// ---------------- launch ----------------------------------------------------
extern "C" void kernel_launch(void* const* d_in, const int* in_sizes, int n_in,
                              void* d_out, int out_size)
{
    (void)in_sizes; (void)n_in; (void)out_size;
    const float* tgt   = (const float*)d_in[0];
    const float* pos   = (const float*)d_in[1];
    const float* ref   = (const float*)d_in[2];
    const float* mem   = (const float*)d_in[3];
    const float* in_w  = (const float*)d_in[6];
    const float* in_b  = (const float*)d_in[7];
    const float* sow   = (const float*)d_in[8];
    const float* sob   = (const float*)d_in[9];
    const float* n1g   = (const float*)d_in[10];
    const float* n1b   = (const float*)d_in[11];
    const float* n2g   = (const float*)d_in[12];
    const float* n2b   = (const float*)d_in[13];
    const float* n3g   = (const float*)d_in[14];
    const float* n3b   = (const float*)d_in[15];
    const float* off_w = (const float*)d_in[16];
    const float* off_b = (const float*)d_in[17];
    const float* aw_w  = (const float*)d_in[18];
    const float* aw_b  = (const float*)d_in[19];
    const float* val_w = (const float*)d_in[20];
    const float* val_b = (const float*)d_in[21];
    const float* cow   = (const float*)d_in[22];
    const float* cob   = (const float*)d_in[23];
    const float* l1w   = (const float*)d_in[24];
    const float* l1b   = (const float*)d_in[25];
    const float* l2w   = (const float*)d_in[26];
    const float* l2b   = (const float*)d_in[27];
    float* out = (float*)d_out;

    float *qin, *cain, *qkv, *o_, *t2, *offb, *awb, *sx, *sy, *sw, *val, *ca, *t3, *ffn;
    cudaGetSymbolAddress((void**)&qin,  g_qin);
    cudaGetSymbolAddress((void**)&cain, g_cain);
    cudaGetSymbolAddress((void**)&qkv,  g_qkv);
    cudaGetSymbolAddress((void**)&o_,   g_o);
    cudaGetSymbolAddress((void**)&t2,   g_t2);
    cudaGetSymbolAddress((void**)&offb, g_off);
    cudaGetSymbolAddress((void**)&awb,  g_aw);
    cudaGetSymbolAddress((void**)&sx,   g_sx);
    cudaGetSymbolAddress((void**)&sy,   g_sy);
    cudaGetSymbolAddress((void**)&sw,   g_sw);
    cudaGetSymbolAddress((void**)&val,  g_val);
    cudaGetSymbolAddress((void**)&ca,   g_ca);
    cudaGetSymbolAddress((void**)&t3,   g_t3);
    cudaGetSymbolAddress((void**)&ffn,  g_ffn);

    auto gg = [](int N, int F) { return dim3((unsigned)(F / 128), (unsigned)((N + 127) / 128)); };
    const int n4 = NTOK * DMODEL / 4;

    // 0) value projection of memory (biggest GEMM) — independent, launch first
    gemm_bf<<<gg(MTOK, 256), 256>>>(mem, val_w, val_b, nullptr, val,
                                    MTOK, 256, 256, 256, 0, 0);
    // 1) qin = tgt + pos
    add_kernel<<<(n4 + 255) / 256, 256>>>((const float4*)tgt, (const float4*)pos,
                                          (float4*)qin, n4);
    // 2-3) QKV projection: q,k from qin; v from tgt
    gemm_bf<<<gg(NTOK, 512), 256>>>(qin, in_w, in_b, nullptr, qkv,
                                    NTOK, 512, 256, 768, 0, 0);
    gemm_bf<<<gg(NTOK, 256), 256>>>(tgt, in_w + 512 * 256, in_b + 512, nullptr, qkv,
                                    NTOK, 256, 256, 768, 512, 0);
    // 4) self attention
    attn_kernel<<<dim3((NQ + 127) / 128, BATCH * HEADS), 128>>>(qkv, o_);
    // 5) out proj + residual(tgt), then LN2 -> t2
    gemm_bf<<<gg(NTOK, 256), 256>>>(o_, sow, sob, tgt, t2,
                                    NTOK, 256, 256, 256, 0, 0);
    ln_kernel<<<(NTOK * 32 + 255) / 256, 256>>>(t2, n2g, n2b, NTOK);
    // 6) cain = t2 + pos
    add_kernel<<<(n4 + 255) / 256, 256>>>((const float4*)t2, (const float4*)pos,
                                          (float4*)cain, n4);
    // 7-8) sampling offsets + attention weights from cain
    gemm_bf<<<gg(NTOK, 256), 256>>>(cain, off_w, off_b, nullptr, offb,
                                    NTOK, 256, 256, 256, 0, 0);
    gemm_bf<<<gg(NTOK, 128), 256>>>(cain, aw_w, aw_b, nullptr, awb,
                                    NTOK, 128, 256, 128, 0, 0);
    // 9) softmax + sample coords
    prep_kernel<<<(NTOK * HEADS + 255) / 256, 256>>>(offb, awb, ref, sx, sy, sw);
    // 10) bilinear gather
    gather_kernel<<<(NTOK * HEADS * 32 + 255) / 256, 256>>>(val, sx, sy, sw, ca);
    // 11) ca out proj + residual(t2), LN1 -> t3
    gemm_bf<<<gg(NTOK, 256), 256>>>(ca, cow, cob, t2, t3,
                                    NTOK, 256, 256, 256, 0, 0);
    ln_kernel<<<(NTOK * 32 + 255) / 256, 256>>>(t3, n1g, n1b, NTOK);
    // 12) FFN
    gemm_bf<<<gg(NTOK, 1024), 256>>>(t3, l1w, l1b, nullptr, ffn,
                                     NTOK, 1024, 256, 1024, 0, 1);
    gemm_bf<<<gg(NTOK, 256), 256>>>(ffn, l2w, l2b, t3, out,
                                    NTOK, 256, 1024, 256, 0, 0);
    ln_kernel<<<(NTOK * 32 + 255) / 256, 256>>>(out, n3g, n3b, NTOK);
}

// round 9
// speedup vs baseline: 2.0138x; 1.0280x over previous
#include <cuda_runtime.h>
#include <cuda_bf16.h>
#include <math.h>
#include <stdint.h>

// Problem constants (fixed by the reference)
#define NQ    900
#define BATCH 8
#define NTOK  (NQ*BATCH)        // 7200
#define DMODEL 256
#define HEADS 8
#define DFF   1024
#define S_TOT 19947
#define MTOK  (S_TOT*BATCH)     // 159576

// ---------------- scratch (static device arrays; no allocation) -------------
__device__ float g_qin[NTOK*DMODEL];
__device__ float g_cain[NTOK*DMODEL];
__device__ float g_qkv[NTOK*768];
__device__ float g_o  [NTOK*DMODEL];
__device__ float g_t2 [NTOK*DMODEL];
__device__ float g_off[NTOK*256];
__device__ float g_aw [NTOK*128];
__device__ float g_sx [NTOK*HEADS*16];
__device__ float g_sy [NTOK*HEADS*16];
__device__ float g_sw [NTOK*HEADS*16];
__device__ float g_val[(size_t)MTOK*DMODEL];
__device__ float g_ca [NTOK*DMODEL];
__device__ float g_t3 [NTOK*DMODEL];
__device__ float g_ffn[NTOK*DFF];

// ---------------- fast exp (FMA pipe, avoids MUFU bottleneck) ---------------
__device__ __forceinline__ float fexp(float x) {
    x = fmaxf(x, -80.f);
    float t  = x * 1.4426950408889634f;
    float fl = floorf(t);
    float f  = t - fl;
    float p  = 1.5403530e-4f;
    p = fmaf(p, f, 1.3333558e-3f);
    p = fmaf(p, f, 9.6181291e-3f);
    p = fmaf(p, f, 5.5504109e-2f);
    p = fmaf(p, f, 2.4022651e-1f);
    p = fmaf(p, f, 6.9314718e-1f);
    p = fmaf(p, f, 1.0f);
    int ei = (int)fl;
    float sc = __int_as_float((ei + 127) << 23);
    return p * sc;
}

// ---------------- bf16 split-pack helpers ------------------------------------
__device__ __forceinline__ void pairsplit(float x, float y, uint32_t& h, uint32_t& l) {
    __nv_bfloat162 hb = __floats2bfloat162_rn(x, y);
    float hx = __bfloat162float(__low2bfloat16(hb));
    float hy = __bfloat162float(__high2bfloat16(hb));
    __nv_bfloat162 lb = __floats2bfloat162_rn(x - hx, y - hy);
    h = *(uint32_t*)&hb;
    l = *(uint32_t*)&lb;
}

#define MMA_BF16(d, a, b)                                                     \
  asm volatile("mma.sync.aligned.m16n8k16.row.col.f32.bf16.bf16.f32 "         \
      "{%0,%1,%2,%3}, {%4,%5,%6,%7}, {%8,%9}, {%0,%1,%2,%3};"                 \
      : "+f"(d[0]), "+f"(d[1]), "+f"(d[2]), "+f"(d[3])                        \
      : "r"(a[0]), "r"(a[1]), "r"(a[2]), "r"(a[3]), "r"(b[0]), "r"(b[1]))

#define LDSM4(R, addr)                                                        \
  asm volatile("ldmatrix.sync.aligned.m8n8.x4.shared.b16 {%0,%1,%2,%3}, [%4];"\
      : "=r"((R)[0]), "=r"((R)[1]), "=r"((R)[2]), "=r"((R)[3]) : "r"(addr))

// ---------------- tensor-core NT GEMM:  C[n,f] = A[n,:]·W[f,:] + bias -------
// A row-major [N,K]; W row-major [F,K]. F multiple of 128, K multiple of 16.
// Compensated bf16 (2-way split, 3 mmas) => ~1e-6 relative accuracy.
// BM=BN=128, BK=16, 256 threads, warp grid 2(m) x 4(n), warp tile 64x32.
// Fragments via ldmatrix.x4; 2 CTAs/SM for latency hiding.
__global__ void __launch_bounds__(256, 2)
gemm_bf(const float* __restrict__ A, const float* __restrict__ W,
        const float* __restrict__ bias, const float* __restrict__ Res,
        float* __restrict__ C, int N, int F, int K, int ldc, int coff, int relu)
{
    // packed bf16x2 tiles, split hi/lo; 8 words of data per row, stride 12.
    __shared__ uint32_t Ah[2][128][12];
    __shared__ uint32_t Al[2][128][12];
    __shared__ uint32_t Bh[2][128][12];
    __shared__ uint32_t Bl[2][128][12];
    const uint32_t BUFB = 128 * 12 * 4;   // bytes per buffer

    const int t    = threadIdx.x;
    const int row0 = blockIdx.y * 128, col0 = blockIdx.x * 128;
    const int lrow = t >> 1;            // 0..127
    const int lh   = t & 1;             // k-half: floats +8*lh, words +4*lh
    const int wid  = t >> 5, lane = t & 31;
    const int wm   = (wid >> 2) * 64;   // 0 or 64
    const int wn   = (wid & 3) * 32;    // 0,32,64,96
    const int g    = lane >> 2, c = lane & 3;

    // ldmatrix per-lane base addresses (buffer 0)
    const uint32_t bAh = (uint32_t)__cvta_generic_to_shared(&Ah[0][0][0]);
    const uint32_t bAl = (uint32_t)__cvta_generic_to_shared(&Al[0][0][0]);
    const uint32_t bBh = (uint32_t)__cvta_generic_to_shared(&Bh[0][0][0]);
    const uint32_t bBl = (uint32_t)__cvta_generic_to_shared(&Bl[0][0][0]);
    const int arow  = lane & 15;             // A: rows 0..15 of the 16x16 frag
    const int akoff = (lane >> 4) * 16;      // +16B for k8..15 half
    uint32_t aAh[4], aAl[4];
#pragma unroll
    for (int mi = 0; mi < 4; mi++) {
        uint32_t off = (uint32_t)((wm + mi * 16 + arow) * 48 + akoff);
        aAh[mi] = bAh + off;
        aAl[mi] = bAl + off;
    }
    const int brow  = (lane & 7) + ((lane >> 4) << 3);  // n row within 16
    const int bkoff = ((lane >> 3) & 1) * 16;           // k-half byte offset
    uint32_t aBh[2], aBl[2];
#pragma unroll
    for (int njp = 0; njp < 2; njp++) {
        uint32_t off = (uint32_t)((wn + njp * 16 + brow) * 48 + bkoff);
        aBh[njp] = bBh + off;
        aBl[njp] = bBl + off;
    }

    float acc[4][4][4];
#pragma unroll
    for (int mi = 0; mi < 4; mi++)
#pragma unroll
        for (int nj = 0; nj < 4; nj++)
#pragma unroll
            for (int e = 0; e < 4; e++) acc[mi][nj][e] = 0.f;

    const int nk = K >> 4;

    auto loadA = [&](int kg, float4& u, float4& v) {
        int gr = row0 + lrow;
        if (gr < N) {
            const float* p = A + (size_t)gr * K + kg + lh * 8;
            u = *(const float4*)p;
            v = *(const float4*)(p + 4);
        } else {
            u = make_float4(0.f, 0.f, 0.f, 0.f);
            v = u;
        }
    };
    auto loadB = [&](int kg, float4& u, float4& v) {
        const float* p = W + (size_t)(col0 + lrow) * K + kg + lh * 8;
        u = *(const float4*)p;
        v = *(const float4*)(p + 4);
    };
    auto storeT = [&](uint32_t (*Th)[128][12], uint32_t (*Tl)[128][12],
                      int b, float4 u, float4 v) {
        uint32_t h0, h1, h2, h3, l0, l1, l2, l3;
        pairsplit(u.x, u.y, h0, l0);
        pairsplit(u.z, u.w, h1, l1);
        pairsplit(v.x, v.y, h2, l2);
        pairsplit(v.z, v.w, h3, l3);
        *(uint4*)&Th[b][lrow][lh * 4] = make_uint4(h0, h1, h2, h3);
        *(uint4*)&Tl[b][lrow][lh * 4] = make_uint4(l0, l1, l2, l3);
    };

    // --- prologue: tile 0 -> buffer 0 ---
    {
        float4 au, av, bu, bv;
        loadA(0, au, av);
        loadB(0, bu, bv);
        storeT(Ah, Al, 0, au, av);
        storeT(Bh, Bl, 0, bu, bv);
    }
    __syncthreads();

    for (int kt = 0; kt < nk; kt++) {
        const uint32_t bo = (kt & 1) ? BUFB : 0u;
        const bool pf = (kt + 1 < nk);
        float4 au, av, bu, bv;
        if (pf) {
            loadA((kt + 1) << 4, au, av);
            loadB((kt + 1) << 4, bu, bv);
        }

        uint32_t ah[4][4], alr[4][4], bh[4][2], blr[4][2];
#pragma unroll
        for (int mi = 0; mi < 4; mi++) {
            LDSM4(ah[mi],  aAh[mi] + bo);
            LDSM4(alr[mi], aAl[mi] + bo);
        }
#pragma unroll
        for (int njp = 0; njp < 2; njp++) {
            uint32_t bt[4], bt2[4];
            LDSM4(bt,  aBh[njp] + bo);
            LDSM4(bt2, aBl[njp] + bo);
            bh[njp*2  ][0] = bt[0];  bh[njp*2  ][1] = bt[1];
            bh[njp*2+1][0] = bt[2];  bh[njp*2+1][1] = bt[3];
            blr[njp*2  ][0] = bt2[0]; blr[njp*2  ][1] = bt2[1];
            blr[njp*2+1][0] = bt2[2]; blr[njp*2+1][1] = bt2[3];
        }
#pragma unroll
        for (int mi = 0; mi < 4; mi++)
#pragma unroll
            for (int nj = 0; nj < 4; nj++) {
                MMA_BF16(acc[mi][nj], ah[mi],  bh[nj]);
                MMA_BF16(acc[mi][nj], alr[mi], bh[nj]);
                MMA_BF16(acc[mi][nj], ah[mi],  blr[nj]);
            }

        if (pf) {
            const int nb = (kt & 1) ^ 1;
            storeT(Ah, Al, nb, au, av);
            storeT(Bh, Bl, nb, bu, bv);
        }
        __syncthreads();
    }

    // --- epilogue ---
#pragma unroll
    for (int mi = 0; mi < 4; mi++) {
#pragma unroll
        for (int h = 0; h < 2; h++) {
            int r = row0 + wm + mi * 16 + g + h * 8;
            if (r >= N) continue;
#pragma unroll
            for (int nj = 0; nj < 4; nj++) {
                int cc = col0 + wn + nj * 8 + c * 2;
                float v0 = acc[mi][nj][h * 2 + 0] + bias[cc];
                float v1 = acc[mi][nj][h * 2 + 1] + bias[cc + 1];
                if (Res) {
                    v0 += Res[(size_t)r * ldc + coff + cc];
                    v1 += Res[(size_t)r * ldc + coff + cc + 1];
                }
                if (relu) { v0 = fmaxf(v0, 0.f); v1 = fmaxf(v1, 0.f); }
                float* cp = C + (size_t)r * ldc + coff + cc;
                cp[0] = v0; cp[1] = v1;
            }
        }
    }
}

// ---------------- elementwise add (vectorized) -------------------------------
__global__ void add_kernel(const float4* __restrict__ a, const float4* __restrict__ b,
                           float4* __restrict__ o, int n4)
{
    int i = blockIdx.x * blockDim.x + threadIdx.x;
    if (i < n4) {
        float4 x = a[i], y = b[i];
        x.x += y.x; x.y += y.y; x.z += y.z; x.w += y.w;
        o[i] = x;
    }
}

// ---------------- flash self-attention, one query row / thread --------------
__global__ void __launch_bounds__(128)
attn_kernel(const float* __restrict__ qkv, float* __restrict__ o)
{
    const int bh = blockIdx.y;
    const int b = bh >> 3, h = bh & 7;
    const int qrow = blockIdx.x * 128 + threadIdx.x;
    const bool valid = qrow < NQ;

    float4 q[8];
    if (valid) {
        const float* qp = qkv + (size_t)(qrow * BATCH + b) * 768 + h * 32;
#pragma unroll
        for (int d = 0; d < 8; d++) {
            float4 v = *(const float4*)(qp + d * 4);
            const float s = 0.17677669529663687f;   // 1/sqrt(32)
            q[d].x = v.x * s; q[d].y = v.y * s; q[d].z = v.z * s; q[d].w = v.w * s;
        }
    }
    float4 acc[8];
#pragma unroll
    for (int d = 0; d < 8; d++) acc[d] = make_float4(0.f, 0.f, 0.f, 0.f);
    float mmax = -1e30f, lsum = 0.f;

    __shared__ float Ks[1024], Vs[1024];

    for (int m0 = 0; m0 < NQ; m0 += 32) {
        int nrows = min(32, NQ - m0);
        {
            int fi = threadIdx.x * 8;
            int r = fi >> 5, d0 = fi & 31;
            if (r < nrows) {
                const float* kp = qkv + (size_t)((m0 + r) * BATCH + b) * 768 + 256 + h * 32 + d0;
                *(float4*)(Ks + fi)     = *(const float4*)kp;
                *(float4*)(Ks + fi + 4) = *(const float4*)(kp + 4);
                const float* vp = kp + 256;
                *(float4*)(Vs + fi)     = *(const float4*)vp;
                *(float4*)(Vs + fi + 4) = *(const float4*)(vp + 4);
            }
        }
        __syncthreads();

        if (valid) {
            float s[32];
            float tmax = -1e30f;
            for (int j = 0; j < nrows; j++) {
                const float4* kr = (const float4*)(Ks + j * 32);
                float d0 = 0.f, d1 = 0.f, d2 = 0.f, d3 = 0.f;
#pragma unroll
                for (int d = 0; d < 8; d++) {
                    float4 kv = kr[d];
                    d0 = fmaf(q[d].x, kv.x, d0);
                    d1 = fmaf(q[d].y, kv.y, d1);
                    d2 = fmaf(q[d].z, kv.z, d2);
                    d3 = fmaf(q[d].w, kv.w, d3);
                }
                s[j] = (d0 + d1) + (d2 + d3);
                tmax = fmaxf(tmax, s[j]);
            }
            float mnew = fmaxf(mmax, tmax);
            float corr = fexp(mmax - mnew);
            lsum *= corr;
#pragma unroll
            for (int d = 0; d < 8; d++) {
                acc[d].x *= corr; acc[d].y *= corr; acc[d].z *= corr; acc[d].w *= corr;
            }
            for (int j = 0; j < nrows; j++) {
                float p = fexp(s[j] - mnew);
                lsum += p;
                const float4* vr = (const float4*)(Vs + j * 32);
#pragma unroll
                for (int d = 0; d < 8; d++) {
                    float4 vv = vr[d];
                    acc[d].x = fmaf(p, vv.x, acc[d].x);
                    acc[d].y = fmaf(p, vv.y, acc[d].y);
                    acc[d].z = fmaf(p, vv.z, acc[d].z);
                    acc[d].w = fmaf(p, vv.w, acc[d].w);
                }
            }
            mmax = mnew;
        }
        __syncthreads();
    }

    if (valid) {
        float inv = 1.f / lsum;
        float* op = o + (size_t)(qrow * BATCH + b) * DMODEL + h * 32;
#pragma unroll
        for (int d = 0; d < 8; d++) {
            float4 v;
            v.x = acc[d].x * inv; v.y = acc[d].y * inv;
            v.z = acc[d].z * inv; v.w = acc[d].w * inv;
            *(float4*)(op + d * 4) = v;
        }
    }
}

// ---------------- LayerNorm, in-place, warp per row (256 cols) --------------
__global__ void ln_kernel(float* __restrict__ x, const float* __restrict__ g,
                          const float* __restrict__ bt, int rows)
{
    int gid = blockIdx.x * blockDim.x + threadIdx.x;
    int r = gid >> 5;
    if (r >= rows) return;
    int lane = gid & 31;
    float* row = x + (size_t)r * 256;
    float v[8]; float s = 0.f;
#pragma unroll
    for (int i = 0; i < 8; i++) { v[i] = row[lane + i * 32]; s += v[i]; }
#pragma unroll
    for (int o = 16; o > 0; o >>= 1) s += __shfl_xor_sync(0xffffffffu, s, o);
    float mean = s * (1.f / 256.f);
    float vs = 0.f;
#pragma unroll
    for (int i = 0; i < 8; i++) { float d = v[i] - mean; vs = fmaf(d, d, vs); }
#pragma unroll
    for (int o = 16; o > 0; o >>= 1) vs += __shfl_xor_sync(0xffffffffu, vs, o);
    float rst = rsqrtf(vs * (1.f / 256.f) + 1e-5f);
#pragma unroll
    for (int i = 0; i < 8; i++) {
        int c = lane + i * 32;
        row[c] = (v[i] - mean) * rst * g[c] + bt[c];
    }
}

// ---------------- deform-attn sampling precompute ---------------------------
__global__ void prep_kernel(const float* __restrict__ off, const float* __restrict__ aw,
                            const float* __restrict__ ref,
                            float* __restrict__ sx, float* __restrict__ sy,
                            float* __restrict__ sw)
{
    int idx = blockIdx.x * blockDim.x + threadIdx.x;
    if (idx >= NTOK * HEADS) return;
    int n = idx >> 3, h = idx & 7;
    const float* op = off + (size_t)n * 256 + h * 32;
    const float* ap = aw  + (size_t)n * 128 + h * 16;
    const float* rp = ref + (size_t)n * 16;

    float a[16]; float mx = -1e30f;
#pragma unroll
    for (int t = 0; t < 16; t++) { a[t] = ap[t]; mx = fmaxf(mx, a[t]); }
    float ssum = 0.f;
#pragma unroll
    for (int t = 0; t < 16; t++) { a[t] = fexp(a[t] - mx); ssum += a[t]; }
    float inv = 1.f / ssum;

    const float Wd[4] = {150.f, 75.f, 38.f, 19.f};
    const float Hh[4] = {100.f, 50.f, 25.f, 13.f};
#pragma unroll
    for (int l = 0; l < 4; l++) {
        float cx = rp[l*4+0], cy = rp[l*4+1], rw = rp[l*4+2], rh = rp[l*4+3];
#pragma unroll
        for (int p = 0; p < 4; p++) {
            float ox = op[(l*4+p)*2+0], oy = op[(l*4+p)*2+1];
            float lx = fmaf(ox * 0.25f * 0.5f, rw, cx);
            float ly = fmaf(oy * 0.25f * 0.5f, rh, cy);
            int o_ = idx * 16 + l * 4 + p;
            sx[o_] = lx * Wd[l] - 0.5f;
            sy[o_] = ly * Hh[l] - 0.5f;
            sw[o_] = a[l*4+p] * inv;
        }
    }
}

// ---------------- deform-attn gather: warp per (token, head), lane = dh -----
__global__ void gather_kernel(const float* __restrict__ val,
                              const float* __restrict__ sx, const float* __restrict__ sy,
                              const float* __restrict__ sw, float* __restrict__ ca)
{
    int gtid = blockIdx.x * blockDim.x + threadIdx.x;
    int wid = gtid >> 5;
    if (wid >= NTOK * HEADS) return;
    int lane = gtid & 31;
    int n = wid >> 3, h = wid & 7;
    int b = n & 7;

    const int cW[4] = {150, 75, 38, 19};
    const int cH[4] = {100, 50, 25, 13};
    const int cS[4] = {0, 15000, 18750, 19700};

    const float* vbase = val + (size_t)b * 256 + h * 32 + lane;
    float acc = 0.f;
#pragma unroll
    for (int t = 0; t < 16; t++) {
        int l = t >> 2;
        float x = sx[wid * 16 + t];
        float y = sy[wid * 16 + t];
        float w = sw[wid * 16 + t];
        float xf = floorf(x), yf = floorf(y);
        int x0 = (int)xf, y0 = (int)yf;
        float fx = x - xf, fy = y - yf;
        int W_ = cW[l], H_ = cH[l];
#pragma unroll
        for (int dy = 0; dy < 2; dy++) {
            int yi = y0 + dy;
            if (yi < 0 || yi >= H_) continue;
            float wy = dy ? fy : (1.f - fy);
#pragma unroll
            for (int dx = 0; dx < 2; dx++) {
                int xi = x0 + dx;
                if (xi < 0 || xi >= W_) continue;
                float wx = dx ? fx : (1.f - fx);
                int s = cS[l] + yi * W_ + xi;
                acc = fmaf(w * wy * wx, __ldg(vbase + (size_t)s * (BATCH * 256)), acc);
            }
        }
    }
    ca[(size_t)n * 256 + h * 32 + lane] = acc;
}

// ---------------- launch ----------------------------------------------------
extern "C" void kernel_launch(void* const* d_in, const int* in_sizes, int n_in,
                              void* d_out, int out_size)
{
    (void)in_sizes; (void)n_in; (void)out_size;
    const float* tgt   = (const float*)d_in[0];
    const float* pos   = (const float*)d_in[1];
    const float* ref   = (const float*)d_in[2];
    const float* mem   = (const float*)d_in[3];
    const float* in_w  = (const float*)d_in[6];
    const float* in_b  = (const float*)d_in[7];
    const float* sow   = (const float*)d_in[8];
    const float* sob   = (const float*)d_in[9];
    const float* n1g   = (const float*)d_in[10];
    const float* n1b   = (const float*)d_in[11];
    const float* n2g   = (const float*)d_in[12];
    const float* n2b   = (const float*)d_in[13];
    const float* n3g   = (const float*)d_in[14];
    const float* n3b   = (const float*)d_in[15];
    const float* off_w = (const float*)d_in[16];
    const float* off_b = (const float*)d_in[17];
    const float* aw_w  = (const float*)d_in[18];
    const float* aw_b  = (const float*)d_in[19];
    const float* val_w = (const float*)d_in[20];
    const float* val_b = (const float*)d_in[21];
    const float* cow   = (const float*)d_in[22];
    const float* cob   = (const float*)d_in[23];
    const float* l1w   = (const float*)d_in[24];
    const float* l1b   = (const float*)d_in[25];
    const float* l2w   = (const float*)d_in[26];
    const float* l2b   = (const float*)d_in[27];
    float* out = (float*)d_out;

    float *qin, *cain, *qkv, *o_, *t2, *offb, *awb, *sx, *sy, *sw, *val, *ca, *t3, *ffn;
    cudaGetSymbolAddress((void**)&qin,  g_qin);
    cudaGetSymbolAddress((void**)&cain, g_cain);
    cudaGetSymbolAddress((void**)&qkv,  g_qkv);
    cudaGetSymbolAddress((void**)&o_,   g_o);
    cudaGetSymbolAddress((void**)&t2,   g_t2);
    cudaGetSymbolAddress((void**)&offb, g_off);
    cudaGetSymbolAddress((void**)&awb,  g_aw);
    cudaGetSymbolAddress((void**)&sx,   g_sx);
    cudaGetSymbolAddress((void**)&sy,   g_sy);
    cudaGetSymbolAddress((void**)&sw,   g_sw);
    cudaGetSymbolAddress((void**)&val,  g_val);
    cudaGetSymbolAddress((void**)&ca,   g_ca);
    cudaGetSymbolAddress((void**)&t3,   g_t3);
    cudaGetSymbolAddress((void**)&ffn,  g_ffn);

    auto gg = [](int N, int F) { return dim3((unsigned)(F / 128), (unsigned)((N + 127) / 128)); };
    const int n4 = NTOK * DMODEL / 4;

    // 0) value projection of memory (biggest GEMM) — independent, launch first
    gemm_bf<<<gg(MTOK, 256), 256>>>(mem, val_w, val_b, nullptr, val,
                                    MTOK, 256, 256, 256, 0, 0);
    // 1) qin = tgt + pos
    add_kernel<<<(n4 + 255) / 256, 256>>>((const float4*)tgt, (const float4*)pos,
                                          (float4*)qin, n4);
    // 2-3) QKV projection: q,k from qin; v from tgt
    gemm_bf<<<gg(NTOK, 512), 256>>>(qin, in_w, in_b, nullptr, qkv,
                                    NTOK, 512, 256, 768, 0, 0);
    gemm_bf<<<gg(NTOK, 256), 256>>>(tgt, in_w + 512 * 256, in_b + 512, nullptr, qkv,
                                    NTOK, 256, 256, 768, 512, 0);
    // 4) self attention
    attn_kernel<<<dim3((NQ + 127) / 128, BATCH * HEADS), 128>>>(qkv, o_);
    // 5) out proj + residual(tgt), then LN2 -> t2
    gemm_bf<<<gg(NTOK, 256), 256>>>(o_, sow, sob, tgt, t2,
                                    NTOK, 256, 256, 256, 0, 0);
    ln_kernel<<<(NTOK * 32 + 255) / 256, 256>>>(t2, n2g, n2b, NTOK);
    // 6) cain = t2 + pos
    add_kernel<<<(n4 + 255) / 256, 256>>>((const float4*)t2, (const float4*)pos,
                                          (float4*)cain, n4);
    // 7-8) sampling offsets + attention weights from cain
    gemm_bf<<<gg(NTOK, 256), 256>>>(cain, off_w, off_b, nullptr, offb,
                                    NTOK, 256, 256, 256, 0, 0);
    gemm_bf<<<gg(NTOK, 128), 256>>>(cain, aw_w, aw_b, nullptr, awb,
                                    NTOK, 128, 256, 128, 0, 0);
    // 9) softmax + sample coords
    prep_kernel<<<(NTOK * HEADS + 255) / 256, 256>>>(offb, awb, ref, sx, sy, sw);
    // 10) bilinear gather
    gather_kernel<<<(NTOK * HEADS * 32 + 255) / 256, 256>>>(val, sx, sy, sw, ca);
    // 11) ca out proj + residual(t2), LN1 -> t3
    gemm_bf<<<gg(NTOK, 256), 256>>>(ca, cow, cob, t2, t3,
                                    NTOK, 256, 256, 256, 0, 0);
    ln_kernel<<<(NTOK * 32 + 255) / 256, 256>>>(t3, n1g, n1b, NTOK);
    // 12) FFN
    gemm_bf<<<gg(NTOK, 1024), 256>>>(t3, l1w, l1b, nullptr, ffn,
                                     NTOK, 1024, 256, 1024, 0, 1);
    gemm_bf<<<gg(NTOK, 256), 256>>>(ffn, l2w, l2b, t3, out,
                                    NTOK, 256, 1024, 256, 0, 0);
    ln_kernel<<<(NTOK * 32 + 255) / 256, 256>>>(out, n3g, n3b, NTOK);
}

// round 10
// speedup vs baseline: 2.0476x; 1.0168x over previous
#include <cuda_runtime.h>
#include <cuda_bf16.h>
#include <math.h>
#include <stdint.h>

// Problem constants (fixed by the reference)
#define NQ    900
#define BATCH 8
#define NTOK  (NQ*BATCH)        // 7200
#define DMODEL 256
#define HEADS 8
#define DFF   1024
#define S_TOT 19947
#define MTOK  (S_TOT*BATCH)     // 159576

// ---------------- scratch (static device arrays; no allocation) -------------
__device__ float g_qin[NTOK*DMODEL];
__device__ float g_cain[NTOK*DMODEL];
__device__ float g_qkv[NTOK*768];
__device__ float g_o  [NTOK*DMODEL];
__device__ float g_t2 [NTOK*DMODEL];
__device__ float g_off[NTOK*256];
__device__ float g_aw [NTOK*128];
__device__ float g_sx [NTOK*HEADS*16];
__device__ float g_sy [NTOK*HEADS*16];
__device__ float g_sw [NTOK*HEADS*16];
__device__ float g_val[(size_t)MTOK*DMODEL];
__device__ float g_ca [NTOK*DMODEL];
__device__ float g_t3 [NTOK*DMODEL];
__device__ float g_ffn[NTOK*DFF];

// ---------------- fast exp (FMA pipe, avoids MUFU bottleneck) ---------------
__device__ __forceinline__ float fexp(float x) {
    x = fmaxf(x, -80.f);
    float t  = x * 1.4426950408889634f;
    float fl = floorf(t);
    float f  = t - fl;
    float p  = 1.5403530e-4f;
    p = fmaf(p, f, 1.3333558e-3f);
    p = fmaf(p, f, 9.6181291e-3f);
    p = fmaf(p, f, 5.5504109e-2f);
    p = fmaf(p, f, 2.4022651e-1f);
    p = fmaf(p, f, 6.9314718e-1f);
    p = fmaf(p, f, 1.0f);
    int ei = (int)fl;
    float sc = __int_as_float((ei + 127) << 23);
    return p * sc;
}

// ---------------- bf16 split-pack helpers ------------------------------------
__device__ __forceinline__ void pairsplit(float x, float y, uint32_t& h, uint32_t& l) {
    __nv_bfloat162 hb = __floats2bfloat162_rn(x, y);
    float hx = __bfloat162float(__low2bfloat16(hb));
    float hy = __bfloat162float(__high2bfloat16(hb));
    __nv_bfloat162 lb = __floats2bfloat162_rn(x - hx, y - hy);
    h = *(uint32_t*)&hb;
    l = *(uint32_t*)&lb;
}

#define MMA_BF16(d, a, b)                                                     \
  asm volatile("mma.sync.aligned.m16n8k16.row.col.f32.bf16.bf16.f32 "         \
      "{%0,%1,%2,%3}, {%4,%5,%6,%7}, {%8,%9}, {%0,%1,%2,%3};"                 \
      : "+f"(d[0]), "+f"(d[1]), "+f"(d[2]), "+f"(d[3])                        \
      : "r"(a[0]), "r"(a[1]), "r"(a[2]), "r"(a[3]), "r"(b[0]), "r"(b[1]))

#define LDSM4(R, addr)                                                        \
  asm volatile("ldmatrix.sync.aligned.m8n8.x4.shared.b16 {%0,%1,%2,%3}, [%4];"\
      : "=r"((R)[0]), "=r"((R)[1]), "=r"((R)[2]), "=r"((R)[3]) : "r"(addr))

// ---------------- tensor-core NT GEMM:  C[n,f] = A[n,:]·W[f,:] + bias -------
// A row-major [N,K]; W row-major [F,K]. F multiple of 128, K multiple of 16.
// Compensated bf16 (2-way split, 3 mmas) => ~1e-6 relative accuracy.
// BM=BN=128, BK=16, 256 threads, warp grid 2(m) x 4(n), warp tile 64x32.
// Fragments via ldmatrix.x4; 2 CTAs/SM for latency hiding.
__global__ void __launch_bounds__(256, 2)
gemm_bf(const float* __restrict__ A, const float* __restrict__ W,
        const float* __restrict__ bias, const float* __restrict__ Res,
        float* __restrict__ C, int N, int F, int K, int ldc, int coff, int relu)
{
    // packed bf16x2 tiles, split hi/lo; 8 words of data per row, stride 12.
    __shared__ uint32_t Ah[2][128][12];
    __shared__ uint32_t Al[2][128][12];
    __shared__ uint32_t Bh[2][128][12];
    __shared__ uint32_t Bl[2][128][12];
    const uint32_t BUFB = 128 * 12 * 4;   // bytes per buffer

    const int t    = threadIdx.x;
    const int row0 = blockIdx.y * 128, col0 = blockIdx.x * 128;
    const int lrow = t >> 1;            // 0..127
    const int lh   = t & 1;             // k-half: floats +8*lh, words +4*lh
    const int wid  = t >> 5, lane = t & 31;
    const int wm   = (wid >> 2) * 64;   // 0 or 64
    const int wn   = (wid & 3) * 32;    // 0,32,64,96
    const int g    = lane >> 2, c = lane & 3;

    // ldmatrix per-lane base addresses (buffer 0)
    const uint32_t bAh = (uint32_t)__cvta_generic_to_shared(&Ah[0][0][0]);
    const uint32_t bAl = (uint32_t)__cvta_generic_to_shared(&Al[0][0][0]);
    const uint32_t bBh = (uint32_t)__cvta_generic_to_shared(&Bh[0][0][0]);
    const uint32_t bBl = (uint32_t)__cvta_generic_to_shared(&Bl[0][0][0]);
    const int arow  = lane & 15;             // A: rows 0..15 of the 16x16 frag
    const int akoff = (lane >> 4) * 16;      // +16B for k8..15 half
    uint32_t aAh[4], aAl[4];
#pragma unroll
    for (int mi = 0; mi < 4; mi++) {
        uint32_t off = (uint32_t)((wm + mi * 16 + arow) * 48 + akoff);
        aAh[mi] = bAh + off;
        aAl[mi] = bAl + off;
    }
    const int brow  = (lane & 7) + ((lane >> 4) << 3);  // n row within 16
    const int bkoff = ((lane >> 3) & 1) * 16;           // k-half byte offset
    uint32_t aBh[2], aBl[2];
#pragma unroll
    for (int njp = 0; njp < 2; njp++) {
        uint32_t off = (uint32_t)((wn + njp * 16 + brow) * 48 + bkoff);
        aBh[njp] = bBh + off;
        aBl[njp] = bBl + off;
    }

    float acc[4][4][4];
#pragma unroll
    for (int mi = 0; mi < 4; mi++)
#pragma unroll
        for (int nj = 0; nj < 4; nj++)
#pragma unroll
            for (int e = 0; e < 4; e++) acc[mi][nj][e] = 0.f;

    const int nk = K >> 4;

    auto loadA = [&](int kg, float4& u, float4& v) {
        int gr = row0 + lrow;
        if (gr < N) {
            const float* p = A + (size_t)gr * K + kg + lh * 8;
            u = *(const float4*)p;
            v = *(const float4*)(p + 4);
        } else {
            u = make_float4(0.f, 0.f, 0.f, 0.f);
            v = u;
        }
    };
    auto loadB = [&](int kg, float4& u, float4& v) {
        const float* p = W + (size_t)(col0 + lrow) * K + kg + lh * 8;
        u = *(const float4*)p;
        v = *(const float4*)(p + 4);
    };
    auto storeT = [&](uint32_t (*Th)[128][12], uint32_t (*Tl)[128][12],
                      int b, float4 u, float4 v) {
        uint32_t h0, h1, h2, h3, l0, l1, l2, l3;
        pairsplit(u.x, u.y, h0, l0);
        pairsplit(u.z, u.w, h1, l1);
        pairsplit(v.x, v.y, h2, l2);
        pairsplit(v.z, v.w, h3, l3);
        *(uint4*)&Th[b][lrow][lh * 4] = make_uint4(h0, h1, h2, h3);
        *(uint4*)&Tl[b][lrow][lh * 4] = make_uint4(l0, l1, l2, l3);
    };

    // --- prologue: tile 0 -> buffer 0 ---
    {
        float4 au, av, bu, bv;
        loadA(0, au, av);
        loadB(0, bu, bv);
        storeT(Ah, Al, 0, au, av);
        storeT(Bh, Bl, 0, bu, bv);
    }
    __syncthreads();

    for (int kt = 0; kt < nk; kt++) {
        const uint32_t bo = (kt & 1) ? BUFB : 0u;
        const bool pf = (kt + 1 < nk);
        float4 au, av, bu, bv;
        if (pf) {
            loadA((kt + 1) << 4, au, av);
            loadB((kt + 1) << 4, bu, bv);
        }

        uint32_t ah[4][4], alr[4][4], bh[4][2], blr[4][2];
#pragma unroll
        for (int mi = 0; mi < 4; mi++) {
            LDSM4(ah[mi],  aAh[mi] + bo);
            LDSM4(alr[mi], aAl[mi] + bo);
        }
#pragma unroll
        for (int njp = 0; njp < 2; njp++) {
            uint32_t bt[4], bt2[4];
            LDSM4(bt,  aBh[njp] + bo);
            LDSM4(bt2, aBl[njp] + bo);
            bh[njp*2  ][0] = bt[0];  bh[njp*2  ][1] = bt[1];
            bh[njp*2+1][0] = bt[2];  bh[njp*2+1][1] = bt[3];
            blr[njp*2  ][0] = bt2[0]; blr[njp*2  ][1] = bt2[1];
            blr[njp*2+1][0] = bt2[2]; blr[njp*2+1][1] = bt2[3];
        }
#pragma unroll
        for (int mi = 0; mi < 4; mi++)
#pragma unroll
            for (int nj = 0; nj < 4; nj++) {
                MMA_BF16(acc[mi][nj], ah[mi],  bh[nj]);
                MMA_BF16(acc[mi][nj], alr[mi], bh[nj]);
                MMA_BF16(acc[mi][nj], ah[mi],  blr[nj]);
            }

        if (pf) {
            const int nb = (kt & 1) ^ 1;
            storeT(Ah, Al, nb, au, av);
            storeT(Bh, Bl, nb, bu, bv);
        }
        __syncthreads();
    }

    // --- epilogue ---
#pragma unroll
    for (int mi = 0; mi < 4; mi++) {
#pragma unroll
        for (int h = 0; h < 2; h++) {
            int r = row0 + wm + mi * 16 + g + h * 8;
            if (r >= N) continue;
#pragma unroll
            for (int nj = 0; nj < 4; nj++) {
                int cc = col0 + wn + nj * 8 + c * 2;
                float v0 = acc[mi][nj][h * 2 + 0] + bias[cc];
                float v1 = acc[mi][nj][h * 2 + 1] + bias[cc + 1];
                if (Res) {
                    v0 += Res[(size_t)r * ldc + coff + cc];
                    v1 += Res[(size_t)r * ldc + coff + cc + 1];
                }
                if (relu) { v0 = fmaxf(v0, 0.f); v1 = fmaxf(v1, 0.f); }
                float* cp = C + (size_t)r * ldc + coff + cc;
                cp[0] = v0; cp[1] = v1;
            }
        }
    }
}

// ---------------- elementwise add (vectorized) -------------------------------
__global__ void add_kernel(const float4* __restrict__ a, const float4* __restrict__ b,
                           float4* __restrict__ o, int n4)
{
    int i = blockIdx.x * blockDim.x + threadIdx.x;
    if (i < n4) {
        float4 x = a[i], y = b[i];
        x.x += y.x; x.y += y.y; x.z += y.z; x.w += y.w;
        o[i] = x;
    }
}

// ---------------- flash self-attention, one query row / thread --------------
__global__ void __launch_bounds__(128)
attn_kernel(const float* __restrict__ qkv, float* __restrict__ o)
{
    const int bh = blockIdx.y;
    const int b = bh >> 3, h = bh & 7;
    const int qrow = blockIdx.x * 128 + threadIdx.x;
    const bool valid = qrow < NQ;

    float4 q[8];
    if (valid) {
        const float* qp = qkv + (size_t)(qrow * BATCH + b) * 768 + h * 32;
#pragma unroll
        for (int d = 0; d < 8; d++) {
            float4 v = *(const float4*)(qp + d * 4);
            const float s = 0.17677669529663687f;   // 1/sqrt(32)
            q[d].x = v.x * s; q[d].y = v.y * s; q[d].z = v.z * s; q[d].w = v.w * s;
        }
    }
    float4 acc[8];
#pragma unroll
    for (int d = 0; d < 8; d++) acc[d] = make_float4(0.f, 0.f, 0.f, 0.f);
    float mmax = -1e30f, lsum = 0.f;

    __shared__ float Ks[1024], Vs[1024];

    for (int m0 = 0; m0 < NQ; m0 += 32) {
        int nrows = min(32, NQ - m0);
        {
            int fi = threadIdx.x * 8;
            int r = fi >> 5, d0 = fi & 31;
            if (r < nrows) {
                const float* kp = qkv + (size_t)((m0 + r) * BATCH + b) * 768 + 256 + h * 32 + d0;
                *(float4*)(Ks + fi)     = *(const float4*)kp;
                *(float4*)(Ks + fi + 4) = *(const float4*)(kp + 4);
                const float* vp = kp + 256;
                *(float4*)(Vs + fi)     = *(const float4*)vp;
                *(float4*)(Vs + fi + 4) = *(const float4*)(vp + 4);
            }
        }
        __syncthreads();

        if (valid) {
            float s[32];
            float tmax = -1e30f;
            for (int j = 0; j < nrows; j++) {
                const float4* kr = (const float4*)(Ks + j * 32);
                float d0 = 0.f, d1 = 0.f, d2 = 0.f, d3 = 0.f;
#pragma unroll
                for (int d = 0; d < 8; d++) {
                    float4 kv = kr[d];
                    d0 = fmaf(q[d].x, kv.x, d0);
                    d1 = fmaf(q[d].y, kv.y, d1);
                    d2 = fmaf(q[d].z, kv.z, d2);
                    d3 = fmaf(q[d].w, kv.w, d3);
                }
                s[j] = (d0 + d1) + (d2 + d3);
                tmax = fmaxf(tmax, s[j]);
            }
            float mnew = fmaxf(mmax, tmax);
            float corr = fexp(mmax - mnew);
            lsum *= corr;
#pragma unroll
            for (int d = 0; d < 8; d++) {
                acc[d].x *= corr; acc[d].y *= corr; acc[d].z *= corr; acc[d].w *= corr;
            }
            for (int j = 0; j < nrows; j++) {
                float p = fexp(s[j] - mnew);
                lsum += p;
                const float4* vr = (const float4*)(Vs + j * 32);
#pragma unroll
                for (int d = 0; d < 8; d++) {
                    float4 vv = vr[d];
                    acc[d].x = fmaf(p, vv.x, acc[d].x);
                    acc[d].y = fmaf(p, vv.y, acc[d].y);
                    acc[d].z = fmaf(p, vv.z, acc[d].z);
                    acc[d].w = fmaf(p, vv.w, acc[d].w);
                }
            }
            mmax = mnew;
        }
        __syncthreads();
    }

    if (valid) {
        float inv = 1.f / lsum;
        float* op = o + (size_t)(qrow * BATCH + b) * DMODEL + h * 32;
#pragma unroll
        for (int d = 0; d < 8; d++) {
            float4 v;
            v.x = acc[d].x * inv; v.y = acc[d].y * inv;
            v.z = acc[d].z * inv; v.w = acc[d].w * inv;
            *(float4*)(op + d * 4) = v;
        }
    }
}

// ---------------- LayerNorm, in-place, warp per row (256 cols) --------------
__global__ void ln_kernel(float* __restrict__ x, const float* __restrict__ g,
                          const float* __restrict__ bt, int rows)
{
    int gid = blockIdx.x * blockDim.x + threadIdx.x;
    int r = gid >> 5;
    if (r >= rows) return;
    int lane = gid & 31;
    float* row = x + (size_t)r * 256;
    float v[8]; float s = 0.f;
#pragma unroll
    for (int i = 0; i < 8; i++) { v[i] = row[lane + i * 32]; s += v[i]; }
#pragma unroll
    for (int o = 16; o > 0; o >>= 1) s += __shfl_xor_sync(0xffffffffu, s, o);
    float mean = s * (1.f / 256.f);
    float vs = 0.f;
#pragma unroll
    for (int i = 0; i < 8; i++) { float d = v[i] - mean; vs = fmaf(d, d, vs); }
#pragma unroll
    for (int o = 16; o > 0; o >>= 1) vs += __shfl_xor_sync(0xffffffffu, vs, o);
    float rst = rsqrtf(vs * (1.f / 256.f) + 1e-5f);
#pragma unroll
    for (int i = 0; i < 8; i++) {
        int c = lane + i * 32;
        row[c] = (v[i] - mean) * rst * g[c] + bt[c];
    }
}

// ---------------- deform-attn sampling precompute ---------------------------
__global__ void prep_kernel(const float* __restrict__ off, const float* __restrict__ aw,
                            const float* __restrict__ ref,
                            float* __restrict__ sx, float* __restrict__ sy,
                            float* __restrict__ sw)
{
    int idx = blockIdx.x * blockDim.x + threadIdx.x;
    if (idx >= NTOK * HEADS) return;
    int n = idx >> 3, h = idx & 7;
    const float* op = off + (size_t)n * 256 + h * 32;
    const float* ap = aw  + (size_t)n * 128 + h * 16;
    const float* rp = ref + (size_t)n * 16;

    float a[16]; float mx = -1e30f;
#pragma unroll
    for (int t = 0; t < 16; t++) { a[t] = ap[t]; mx = fmaxf(mx, a[t]); }
    float ssum = 0.f;
#pragma unroll
    for (int t = 0; t < 16; t++) { a[t] = fexp(a[t] - mx); ssum += a[t]; }
    float inv = 1.f / ssum;

    const float Wd[4] = {150.f, 75.f, 38.f, 19.f};
    const float Hh[4] = {100.f, 50.f, 25.f, 13.f};
#pragma unroll
    for (int l = 0; l < 4; l++) {
        float cx = rp[l*4+0], cy = rp[l*4+1], rw = rp[l*4+2], rh = rp[l*4+3];
#pragma unroll
        for (int p = 0; p < 4; p++) {
            float ox = op[(l*4+p)*2+0], oy = op[(l*4+p)*2+1];
            float lx = fmaf(ox * 0.25f * 0.5f, rw, cx);
            float ly = fmaf(oy * 0.25f * 0.5f, rh, cy);
            int o_ = idx * 16 + l * 4 + p;
            sx[o_] = lx * Wd[l] - 0.5f;
            sy[o_] = ly * Hh[l] - 0.5f;
            sw[o_] = a[l*4+p] * inv;
        }
    }
}

// ---------------- deform-attn gather: warp per (token, head), lane = dh -----
__global__ void gather_kernel(const float* __restrict__ val,
                              const float* __restrict__ sx, const float* __restrict__ sy,
                              const float* __restrict__ sw, float* __restrict__ ca)
{
    int gtid = blockIdx.x * blockDim.x + threadIdx.x;
    int wid = gtid >> 5;
    if (wid >= NTOK * HEADS) return;
    int lane = gtid & 31;
    int n = wid >> 3, h = wid & 7;
    int b = n & 7;

    const int cW[4] = {150, 75, 38, 19};
    const int cH[4] = {100, 50, 25, 13};
    const int cS[4] = {0, 15000, 18750, 19700};

    const float* vbase = val + (size_t)b * 256 + h * 32 + lane;
    float acc = 0.f;
#pragma unroll
    for (int t = 0; t < 16; t++) {
        int l = t >> 2;
        float x = sx[wid * 16 + t];
        float y = sy[wid * 16 + t];
        float w = sw[wid * 16 + t];
        float xf = floorf(x), yf = floorf(y);
        int x0 = (int)xf, y0 = (int)yf;
        float fx = x - xf, fy = y - yf;
        int W_ = cW[l], H_ = cH[l];
#pragma unroll
        for (int dy = 0; dy < 2; dy++) {
            int yi = y0 + dy;
            if (yi < 0 || yi >= H_) continue;
            float wy = dy ? fy : (1.f - fy);
#pragma unroll
            for (int dx = 0; dx < 2; dx++) {
                int xi = x0 + dx;
                if (xi < 0 || xi >= W_) continue;
                float wx = dx ? fx : (1.f - fx);
                int s = cS[l] + yi * W_ + xi;
                acc = fmaf(w * wy * wx, __ldg(vbase + (size_t)s * (BATCH * 256)), acc);
            }
        }
    }
    ca[(size_t)n * 256 + h * 32 + lane] = acc;
}

// ---------------- launch ----------------------------------------------------
extern "C" void kernel_launch(void* const* d_in, const int* in_sizes, int n_in,
                              void* d_out, int out_size)
{
    (void)in_sizes; (void)n_in; (void)out_size;
    const float* tgt   = (const float*)d_in[0];
    const float* pos   = (const float*)d_in[1];
    const float* ref   = (const float*)d_in[2];
    const float* mem   = (const float*)d_in[3];
    const float* in_w  = (const float*)d_in[6];
    const float* in_b  = (const float*)d_in[7];
    const float* sow   = (const float*)d_in[8];
    const float* sob   = (const float*)d_in[9];
    const float* n1g   = (const float*)d_in[10];
    const float* n1b   = (const float*)d_in[11];
    const float* n2g   = (const float*)d_in[12];
    const float* n2b   = (const float*)d_in[13];
    const float* n3g   = (const float*)d_in[14];
    const float* n3b   = (const float*)d_in[15];
    const float* off_w = (const float*)d_in[16];
    const float* off_b = (const float*)d_in[17];
    const float* aw_w  = (const float*)d_in[18];
    const float* aw_b  = (const float*)d_in[19];
    const float* val_w = (const float*)d_in[20];
    const float* val_b = (const float*)d_in[21];
    const float* cow   = (const float*)d_in[22];
    const float* cob   = (const float*)d_in[23];
    const float* l1w   = (const float*)d_in[24];
    const float* l1b   = (const float*)d_in[25];
    const float* l2w   = (const float*)d_in[26];
    const float* l2b   = (const float*)d_in[27];
    float* out = (float*)d_out;

    float *qin, *cain, *qkv, *o_, *t2, *offb, *awb, *sx, *sy, *sw, *val, *ca, *t3, *ffn;
    cudaGetSymbolAddress((void**)&qin,  g_qin);
    cudaGetSymbolAddress((void**)&cain, g_cain);
    cudaGetSymbolAddress((void**)&qkv,  g_qkv);
    cudaGetSymbolAddress((void**)&o_,   g_o);
    cudaGetSymbolAddress((void**)&t2,   g_t2);
    cudaGetSymbolAddress((void**)&offb, g_off);
    cudaGetSymbolAddress((void**)&awb,  g_aw);
    cudaGetSymbolAddress((void**)&sx,   g_sx);
    cudaGetSymbolAddress((void**)&sy,   g_sy);
    cudaGetSymbolAddress((void**)&sw,   g_sw);
    cudaGetSymbolAddress((void**)&val,  g_val);
    cudaGetSymbolAddress((void**)&ca,   g_ca);
    cudaGetSymbolAddress((void**)&t3,   g_t3);
    cudaGetSymbolAddress((void**)&ffn,  g_ffn);

    // one-time stream/event setup (created on the first, non-captured call)
    static cudaStream_t s2 = nullptr;
    static cudaEvent_t ev_fork = nullptr, ev_join = nullptr;
    if (!s2) {
        cudaStreamCreateWithFlags(&s2, cudaStreamNonBlocking);
        cudaEventCreateWithFlags(&ev_fork, cudaEventDisableTiming);
        cudaEventCreateWithFlags(&ev_join, cudaEventDisableTiming);
    }

    auto gg = [](int N, int F) { return dim3((unsigned)(F / 128), (unsigned)((N + 127) / 128)); };
    const int n4 = NTOK * DMODEL / 4;

    // ---- fork: val projection GEMM runs concurrently on s2 ----
    cudaEventRecord(ev_fork, 0);
    cudaStreamWaitEvent(s2, ev_fork, 0);
    gemm_bf<<<gg(MTOK, 256), 256, 0, s2>>>(mem, val_w, val_b, nullptr, val,
                                           MTOK, 256, 256, 256, 0, 0);
    cudaEventRecord(ev_join, s2);

    // ---- main chain on the capture stream ----
    // 1) qin = tgt + pos
    add_kernel<<<(n4 + 255) / 256, 256>>>((const float4*)tgt, (const float4*)pos,
                                          (float4*)qin, n4);
    // 2-3) QKV projection: q,k from qin; v from tgt
    gemm_bf<<<gg(NTOK, 512), 256>>>(qin, in_w, in_b, nullptr, qkv,
                                    NTOK, 512, 256, 768, 0, 0);
    gemm_bf<<<gg(NTOK, 256), 256>>>(tgt, in_w + 512 * 256, in_b + 512, nullptr, qkv,
                                    NTOK, 256, 256, 768, 512, 0);
    // 4) self attention
    attn_kernel<<<dim3((NQ + 127) / 128, BATCH * HEADS), 128>>>(qkv, o_);
    // 5) out proj + residual(tgt), then LN2 -> t2
    gemm_bf<<<gg(NTOK, 256), 256>>>(o_, sow, sob, tgt, t2,
                                    NTOK, 256, 256, 256, 0, 0);
    ln_kernel<<<(NTOK * 32 + 255) / 256, 256>>>(t2, n2g, n2b, NTOK);
    // 6) cain = t2 + pos
    add_kernel<<<(n4 + 255) / 256, 256>>>((const float4*)t2, (const float4*)pos,
                                          (float4*)cain, n4);
    // 7-8) sampling offsets + attention weights from cain
    gemm_bf<<<gg(NTOK, 256), 256>>>(cain, off_w, off_b, nullptr, offb,
                                    NTOK, 256, 256, 256, 0, 0);
    gemm_bf<<<gg(NTOK, 128), 256>>>(cain, aw_w, aw_b, nullptr, awb,
                                    NTOK, 128, 256, 128, 0, 0);
    // 9) softmax + sample coords
    prep_kernel<<<(NTOK * HEADS + 255) / 256, 256>>>(offb, awb, ref, sx, sy, sw);

    // ---- join: gather needs the val projection ----
    cudaStreamWaitEvent(0, ev_join, 0);

    // 10) bilinear gather
    gather_kernel<<<(NTOK * HEADS * 32 + 255) / 256, 256>>>(val, sx, sy, sw, ca);
    // 11) ca out proj + residual(t2), LN1 -> t3
    gemm_bf<<<gg(NTOK, 256), 256>>>(ca, cow, cob, t2, t3,
                                    NTOK, 256, 256, 256, 0, 0);
    ln_kernel<<<(NTOK * 32 + 255) / 256, 256>>>(t3, n1g, n1b, NTOK);
    // 12) FFN
    gemm_bf<<<gg(NTOK, 1024), 256>>>(t3, l1w, l1b, nullptr, ffn,
                                     NTOK, 1024, 256, 1024, 0, 1);
    gemm_bf<<<gg(NTOK, 256), 256>>>(ffn, l2w, l2b, t3, out,
                                    NTOK, 256, 1024, 256, 0, 0);
    ln_kernel<<<(NTOK * 32 + 255) / 256, 256>>>(out, n3g, n3b, NTOK);
}